// round 14
// baseline (speedup 1.0000x reference)
#include <cuda_runtime.h>
#include <cuda_bf16.h>
#include <math.h>
#include <stdint.h>

// Problem dims
#define B_   4
#define S_   512
#define H_   2048
#define E_   16
#define D_   128
#define GH_  2048
#define G3_  6144
#define NTOK 2048   // B_*S_

// Output layout (flat f32 concat, reference return order)
#define O_MULT 0
#define O_SEL  4096
#define O_EXPR 8192
#define O_HN   4202496
#define O_PEN  4210688
#define O_COS  4210689
#define O_LOSS 4243457

// -------- device scratch --------
__device__ float    g_xi[NTOK * G3_];      // PERM layout: [step][gate][j][b]
__device__ float    g_hs[NTOK * GH_];
__device__ float    g_hbuf[2 * B_ * GH_];
__device__ float    g_pen[NTOK];
__device__ float    g_scal[32];
__device__ float    g_losspart[1024];
__device__ unsigned g_ctr;

// bf16 hi/lo split operands
__device__ __align__(16) __nv_bfloat16 g_xh[NTOK * H_];
__device__ __align__(16) __nv_bfloat16 g_xl[NTOK * H_];
__device__ __align__(16) __nv_bfloat16 g_wih_h[G3_ * H_];
__device__ __align__(16) __nv_bfloat16 g_wih_l[G3_ * H_];
__device__ __align__(16) __nv_bfloat16 g_weT_h[GH_ * H_];
__device__ __align__(16) __nv_bfloat16 g_weT_l[GH_ * H_];

// -------- helpers --------
__device__ __forceinline__ float wsum(float v) {
#pragma unroll
    for (int o = 16; o > 0; o >>= 1) v += __shfl_xor_sync(0xffffffffu, v, o);
    return v;
}
__device__ __forceinline__ uint32_t smem_u32(const void* p) {
    uint32_t a;
    asm("{ .reg .u64 t; cvta.to.shared.u64 t, %1; cvt.u32.u64 %0, t; }"
        : "=r"(a) : "l"(p));
    return a;
}
__device__ __forceinline__ void ldsm4(uint32_t addr, uint32_t* r) {
    asm volatile("ldmatrix.sync.aligned.m8n8.x4.shared.b16 {%0,%1,%2,%3}, [%4];"
                 : "=r"(r[0]), "=r"(r[1]), "=r"(r[2]), "=r"(r[3]) : "r"(addr));
}
__device__ __forceinline__ void mma16816(float* c, const uint32_t* a,
                                         uint32_t b0, uint32_t b1) {
    asm volatile(
        "mma.sync.aligned.m16n8k16.row.col.f32.bf16.bf16.f32 "
        "{%0,%1,%2,%3}, {%4,%5,%6,%7}, {%8,%9}, {%0,%1,%2,%3};"
        : "+f"(c[0]), "+f"(c[1]), "+f"(c[2]), "+f"(c[3])
        : "r"(a[0]), "r"(a[1]), "r"(a[2]), "r"(a[3]), "r"(b0), "r"(b1));
}
__device__ __forceinline__ void cpa16(uint32_t s, const void* g) {
    asm volatile("cp.async.cg.shared.global [%0], [%1], 16;" :: "r"(s), "l"(g));
}
__device__ __forceinline__ void cpa_commit() {
    asm volatile("cp.async.commit_group;");
}
template <int N>
__device__ __forceinline__ void cpa_wait() {
    asm volatile("cp.async.wait_group %0;" :: "n"(N));
}
// Grid barrier: syncthreads chains all threads' .cg stores into thread 0's
// release-arrive (the cooperative-groups grid.sync pattern). Volatile L2
// polling identical to R8. No per-thread MEMBAR.GPU.
__device__ __forceinline__ void gsync(unsigned target) {
    __syncthreads();
    if (threadIdx.x == 0) {
        asm volatile("red.release.gpu.global.add.u32 [%0], %1;"
                     :: "l"(&g_ctr), "r"(1u) : "memory");
        volatile unsigned* p = &g_ctr;
        while (*p < target) { __nanosleep(32); }
    }
    __syncthreads();
}

// -------- init --------
__global__ void init_kernel(const float* __restrict__ hn) {
    int i = blockIdx.x * 256 + threadIdx.x;
    if (i == 0) g_ctr = 0u;
    if (i < B_ * GH_) g_hbuf[i] = hn[i];
}

// -------- split f32 -> bf16 hi/lo --------
__global__ void split_kernel(const float* __restrict__ src,
                             __nv_bfloat16* __restrict__ hi,
                             __nv_bfloat16* __restrict__ lo, int n4) {
    int i = blockIdx.x * 256 + threadIdx.x;
    if (i >= n4) return;
    float4 v = reinterpret_cast<const float4*>(src)[i];
    __nv_bfloat16 h0 = __float2bfloat16(v.x), h1 = __float2bfloat16(v.y);
    __nv_bfloat16 h2 = __float2bfloat16(v.z), h3 = __float2bfloat16(v.w);
    __nv_bfloat16 l0 = __float2bfloat16(v.x - __bfloat162float(h0));
    __nv_bfloat16 l1 = __float2bfloat16(v.y - __bfloat162float(h1));
    __nv_bfloat16 l2 = __float2bfloat16(v.z - __bfloat162float(h2));
    __nv_bfloat16 l3 = __float2bfloat16(v.w - __bfloat162float(h3));
    reinterpret_cast<__nv_bfloat162*>(hi)[2 * i]     = __nv_bfloat162(h0, h1);
    reinterpret_cast<__nv_bfloat162*>(hi)[2 * i + 1] = __nv_bfloat162(h2, h3);
    reinterpret_cast<__nv_bfloat162*>(lo)[2 * i]     = __nv_bfloat162(l0, l1);
    reinterpret_cast<__nv_bfloat162*>(lo)[2 * i + 1] = __nv_bfloat162(l2, l3);
}

// -------- transpose + split: W[H,GH] -> T[GH,H] bf16 hi/lo --------
__global__ void tsplit_kernel(const float* __restrict__ W,
                              __nv_bfloat16* __restrict__ Th,
                              __nv_bfloat16* __restrict__ Tl) {
    __shared__ float t[32][33];
    int gc = blockIdx.x * 32;
    int gr = blockIdx.y * 32;
    int tx = threadIdx.x, ty = threadIdx.y;
#pragma unroll
    for (int r = 0; r < 32; r += 8)
        t[ty + r][tx] = W[(size_t)(gr + ty + r) * GH_ + gc + tx];
    __syncthreads();
#pragma unroll
    for (int r = 0; r < 32; r += 8) {
        float v = t[tx][ty + r];
        __nv_bfloat16 h = __float2bfloat16(v);
        __nv_bfloat16 l = __float2bfloat16(v - __bfloat162float(h));
        size_t o = (size_t)(gc + ty + r) * H_ + gr + tx;
        Th[o] = h; Tl[o] = l;
    }
}

// ========== mma.sync GEMM: C[M,N] = A @ B^T, bf16 hi/lo 3-term split =====
#define ROWB  80
#define TILEB (128 * ROWB)       // 10240
#define BUFB  (4 * TILEB)        // 40960
#define SMTOT (2 * BUFB)         // 81920

template <int EPI>
__global__ void __launch_bounds__(256) mma_gemm_kernel(
    const __nv_bfloat16* __restrict__ Ah, const __nv_bfloat16* __restrict__ Al,
    const __nv_bfloat16* __restrict__ Bh, const __nv_bfloat16* __restrict__ Bl,
    float* __restrict__ C, int N, int K)
{
    extern __shared__ char smem[];
    const uint32_t sb = smem_u32(smem);
    const int t    = threadIdx.x;
    const int lane = t & 31;
    const int w    = t >> 5;
    const int wm   = w >> 1;
    const int wn   = w & 1;
    const int n0   = blockIdx.x * 128;
    const int m0   = blockIdx.y * 128;

    const __nv_bfloat16* srcs[4] = {
        Ah + (size_t)m0 * K, Al + (size_t)m0 * K,
        Bh + (size_t)n0 * K, Bl + (size_t)n0 * K };

    const int srow0 = t >> 2;
    const int srow1 = srow0 + 64;
    const int sc16  = t & 3;

    float acc[2][8][4];
#pragma unroll
    for (int i = 0; i < 2; i++)
#pragma unroll
        for (int j = 0; j < 8; j++)
#pragma unroll
            for (int c = 0; c < 4; c++) acc[i][j][c] = 0.f;

    const uint32_t a_row = wm * 32 + (lane & 15);
    const uint32_t a_cs  = lane >> 4;
    const uint32_t b_row = wn * 64 + ((lane >> 4) << 3) + (lane & 7);
    const uint32_t b_cs  = (lane >> 3) & 1;

    const int NCH = K >> 5;

    auto stage = [&](int ch, int buf) {
        const uint32_t bb = sb + buf * BUFB;
        const int koff = ch * 32 + sc16 * 8;
#pragma unroll
        for (int o = 0; o < 4; o++) {
            cpa16(bb + o * TILEB + srow0 * ROWB + sc16 * 16,
                  srcs[o] + (size_t)srow0 * K + koff);
            cpa16(bb + o * TILEB + srow1 * ROWB + sc16 * 16,
                  srcs[o] + (size_t)srow1 * K + koff);
        }
        cpa_commit();
    };

    stage(0, 0);
#pragma unroll 1
    for (int ch = 0; ch < NCH; ch++) {
        const int buf = ch & 1;
        if (ch + 1 < NCH) { stage(ch + 1, buf ^ 1); cpa_wait<1>(); }
        else              { cpa_wait<0>(); }
        __syncthreads();

        const uint32_t bb = sb + buf * BUFB;
#pragma unroll
        for (int kt = 0; kt < 2; kt++) {
            uint32_t ah[2][4], al[2][4], bhf[4][4], blf[4][4];
#pragma unroll
            for (int mt = 0; mt < 2; mt++) {
                uint32_t off = bb + (a_row + mt * 16) * ROWB + (kt * 2 + a_cs) * 16;
                ldsm4(off, ah[mt]);
                ldsm4(off + TILEB, al[mt]);
            }
#pragma unroll
            for (int ntp = 0; ntp < 4; ntp++) {
                uint32_t off = bb + 2 * TILEB + (b_row + ntp * 16) * ROWB + (kt * 2 + b_cs) * 16;
                ldsm4(off, bhf[ntp]);
                ldsm4(off + TILEB, blf[ntp]);
            }
#pragma unroll
            for (int mt = 0; mt < 2; mt++)
#pragma unroll
                for (int ntp = 0; ntp < 4; ntp++) {
                    mma16816(acc[mt][2 * ntp],     ah[mt], bhf[ntp][0], bhf[ntp][1]);
                    mma16816(acc[mt][2 * ntp + 1], ah[mt], bhf[ntp][2], bhf[ntp][3]);
                }
#pragma unroll
            for (int mt = 0; mt < 2; mt++)
#pragma unroll
                for (int ntp = 0; ntp < 4; ntp++) {
                    mma16816(acc[mt][2 * ntp],     ah[mt], blf[ntp][0], blf[ntp][1]);
                    mma16816(acc[mt][2 * ntp + 1], ah[mt], blf[ntp][2], blf[ntp][3]);
                }
#pragma unroll
            for (int mt = 0; mt < 2; mt++)
#pragma unroll
                for (int ntp = 0; ntp < 4; ntp++) {
                    mma16816(acc[mt][2 * ntp],     al[mt], bhf[ntp][0], bhf[ntp][1]);
                    mma16816(acc[mt][2 * ntp + 1], al[mt], bhf[ntp][2], bhf[ntp][3]);
                }
        }
        __syncthreads();
    }

    const int g  = lane >> 2;
    const int t2 = lane & 3;
    if (EPI == 0) {
#pragma unroll
        for (int mt = 0; mt < 2; mt++) {
            int row = m0 + wm * 32 + mt * 16 + g;
#pragma unroll
            for (int nt = 0; nt < 8; nt++) {
                int col = n0 + wn * 64 + nt * 8 + t2 * 2;
                *reinterpret_cast<float2*>(&C[(size_t)row * N + col]) =
                    make_float2(acc[mt][nt][0], acc[mt][nt][1]);
                *reinterpret_cast<float2*>(&C[(size_t)(row + 8) * N + col]) =
                    make_float2(acc[mt][nt][2], acc[mt][nt][3]);
            }
        }
    } else if (EPI == 2) {
        // xi PERM store: dst ((step*3+gate)*GH+j)*4+b
#pragma unroll
        for (int mt = 0; mt < 2; mt++) {
#pragma unroll
            for (int rr = 0; rr < 2; rr++) {
                int row  = m0 + wm * 32 + mt * 16 + g + rr * 8;
                int b    = row >> 9;
                int st   = row & 511;
#pragma unroll
                for (int nt = 0; nt < 8; nt++) {
                    int col  = n0 + wn * 64 + nt * 8 + t2 * 2;
                    int gate = col >> 11;
                    int j    = col & 2047;
                    size_t base = ((size_t)(st * 3 + gate) * GH_ + j) * 4 + b;
                    C[base]     = acc[mt][nt][rr * 2 + 0];
                    C[base + 4] = acc[mt][nt][rr * 2 + 1];
                }
            }
        }
    } else {
        float s = 0.f;
#pragma unroll
        for (int mt = 0; mt < 2; mt++) {
            int row = m0 + wm * 32 + mt * 16 + g;
#pragma unroll
            for (int nt = 0; nt < 8; nt++) {
                int col = n0 + wn * 64 + nt * 8 + t2 * 2;
                float d0 = acc[mt][nt][0] - (row == col ? 1.f : 0.f);
                float d1 = acc[mt][nt][1] - (row == col + 1 ? 1.f : 0.f);
                float d2 = acc[mt][nt][2] - (row + 8 == col ? 1.f : 0.f);
                float d3 = acc[mt][nt][3] - (row + 8 == col + 1 ? 1.f : 0.f);
                s += d0 * d0 + d1 * d1 + d2 * d2 + d3 * d3;
            }
        }
        float* red = reinterpret_cast<float*>(smem);
        red[t] = s; __syncthreads();
        for (int o = 128; o > 0; o >>= 1) { if (t < o) red[t] += red[t + o]; __syncthreads(); }
        if (t == 0) g_losspart[blockIdx.y * gridDim.x + blockIdx.x] = red[0];
    }
}

// ===== persistent GRU: grid 152, 1024 thr, split-K=2, SoA h (R8 core) =====
__global__ void __launch_bounds__(1024) gru_kernel(const float* __restrict__ w_hh,
                                                   float* __restrict__ out_hn) {
    __shared__ float h_s[4][GH_];     // SoA: [batch][k] -> conflict-free float4 LDS
    __shared__ float part[16][12];
    const int t    = threadIdx.x;
    const int lane = t & 31;
    const int warp = t >> 5;          // 0..31
    const int pair = warp >> 1;       // 0..15
    const int half = warp & 1;
    const int nb   = gridDim.x;
    const int j    = pair * 152 + blockIdx.x;
    const bool valid = (j < GH_);
    unsigned target = 0;

    const float* wr = w_hh + (size_t)j * GH_;
    const float* wz = w_hh + (size_t)(GH_ + j) * GH_;
    const float* wn = w_hh + (size_t)(2 * GH_ + j) * GH_;
    const int kbase = half * 1024 + lane * 4;

    for (int step = 0; step < S_; step++) {
        if (step > 0) { target += nb; gsync(target); }
        const float* hsrc = g_hbuf + (step & 1) * (B_ * GH_);
        // SoA staging: all 1024 threads, 2 float4 each (same values/addresses)
#pragma unroll
        for (int f = 0; f < 2; f++) {
            int i   = t + f * 1024;      // 0..2047
            int b   = i >> 9;
            int idx = i & 511;
            float4 v = __ldcg(reinterpret_cast<const float4*>(hsrc + b * GH_) + idx);
            *reinterpret_cast<float4*>(&h_s[b][idx * 4]) = v;
        }
        __syncthreads();
        float* hdst = g_hbuf + ((step + 1) & 1) * (B_ * GH_);

        float4 ar = make_float4(0.f, 0.f, 0.f, 0.f);
        float4 az = ar, an = ar;
        float xiv = 0.f;
        if (valid) {
            if (half == 0 && lane < 12)
                xiv = __ldcg(g_xi + ((size_t)(step * 3 + (lane >> 2)) * GH_ + j) * 4 + (lane & 3));

#pragma unroll
            for (int it = 0; it < 8; it++) {
                const int k = kbase + it * 128;
                float4 r4 = __ldcg(reinterpret_cast<const float4*>(wr + k));
                float4 z4 = __ldcg(reinterpret_cast<const float4*>(wz + k));
                float4 n4 = __ldcg(reinterpret_cast<const float4*>(wn + k));
                float4 hb0 = *reinterpret_cast<const float4*>(&h_s[0][k]);
                float4 hb1 = *reinterpret_cast<const float4*>(&h_s[1][k]);
                float4 hb2 = *reinterpret_cast<const float4*>(&h_s[2][k]);
                float4 hb3 = *reinterpret_cast<const float4*>(&h_s[3][k]);
                ar.x += r4.x*hb0.x + r4.y*hb0.y + r4.z*hb0.z + r4.w*hb0.w;
                ar.y += r4.x*hb1.x + r4.y*hb1.y + r4.z*hb1.z + r4.w*hb1.w;
                ar.z += r4.x*hb2.x + r4.y*hb2.y + r4.z*hb2.z + r4.w*hb2.w;
                ar.w += r4.x*hb3.x + r4.y*hb3.y + r4.z*hb3.z + r4.w*hb3.w;
                az.x += z4.x*hb0.x + z4.y*hb0.y + z4.z*hb0.z + z4.w*hb0.w;
                az.y += z4.x*hb1.x + z4.y*hb1.y + z4.z*hb1.z + z4.w*hb1.w;
                az.z += z4.x*hb2.x + z4.y*hb2.y + z4.z*hb2.z + z4.w*hb2.w;
                az.w += z4.x*hb3.x + z4.y*hb3.y + z4.z*hb3.z + z4.w*hb3.w;
                an.x += n4.x*hb0.x + n4.y*hb0.y + n4.z*hb0.z + n4.w*hb0.w;
                an.y += n4.x*hb1.x + n4.y*hb1.y + n4.z*hb1.z + n4.w*hb1.w;
                an.z += n4.x*hb2.x + n4.y*hb2.y + n4.z*hb2.z + n4.w*hb2.w;
                an.w += n4.x*hb3.x + n4.y*hb3.y + n4.z*hb3.z + n4.w*hb3.w;
            }

            ar.x = wsum(ar.x); ar.y = wsum(ar.y); ar.z = wsum(ar.z); ar.w = wsum(ar.w);
            az.x = wsum(az.x); az.y = wsum(az.y); az.z = wsum(az.z); az.w = wsum(az.w);
            an.x = wsum(an.x); an.y = wsum(an.y); an.z = wsum(an.z); an.w = wsum(an.w);
            if (half == 1 && lane == 0) {
                part[pair][0]  = ar.x; part[pair][1]  = ar.y;
                part[pair][2]  = ar.z; part[pair][3]  = ar.w;
                part[pair][4]  = az.x; part[pair][5]  = az.y;
                part[pair][6]  = az.z; part[pair][7]  = az.w;
                part[pair][8]  = an.x; part[pair][9]  = an.y;
                part[pair][10] = an.z; part[pair][11] = an.w;
            }
        }
        __syncthreads();
        if (valid && half == 0) {
            int b = lane & 3;
            float xr = __shfl_sync(0xffffffffu, xiv, b);
            float xz = __shfl_sync(0xffffffffu, xiv, 4 + b);
            float xn = __shfl_sync(0xffffffffu, xiv, 8 + b);
            if (lane < 4) {
                float arb = ((b & 1) ? ((b & 2) ? ar.w : ar.y) : ((b & 2) ? ar.z : ar.x))
                            + part[pair][b];
                float azb = ((b & 1) ? ((b & 2) ? az.w : az.y) : ((b & 2) ? az.z : az.x))
                            + part[pair][4 + b];
                float anb = ((b & 1) ? ((b & 2) ? an.w : an.y) : ((b & 2) ? an.z : an.x))
                            + part[pair][8 + b];
                float hob = h_s[b][j];
                float r = 1.f / (1.f + expf(-(xr + arb)));
                float z = 1.f / (1.f + expf(-(xz + azb)));
                float n = tanhf(xn + r * anb);
                float hv = (1.f - z) * n + z * hob;
                __stcg(hdst + b * GH_ + j, hv);
                __stcg(g_hs + (size_t)(b * S_ + step) * GH_ + j, hv);
            }
        }
    }
    target += nb; gsync(target);
    if (blockIdx.x == 0) {
        const float* hf = g_hbuf;   // 512 steps even -> buffer 0
        for (int i = t; i < B_ * GH_; i += 1024) out_hn[i] = __ldcg(hf + i);
    }
}

// -------- per-token: normalize rout, gram penalty, cosine sims --------
__global__ void __launch_bounds__(128) token_kernel(const float* __restrict__ expr,
                                                    float* __restrict__ cosO) {
    const int token = blockIdx.x;
    const int t = threadIdx.x, lane = t & 31, warp = t >> 5;
    __shared__ float sv[16 * 132];
    __shared__ float gm[16][17];
    __shared__ float pen_s[16];
    const float* rout = g_hs + (size_t)token * GH_;

    for (int e = warp; e < 16; e += 4) {
        float s = 0.f;
        for (int d = lane; d < 128; d += 32) { float v = rout[e * 128 + d]; s += v * v; }
        s = wsum(s);
        float inv = 1.f / fmaxf(sqrtf(s), 1e-12f);
        for (int d = lane; d < 128; d += 32) sv[e * 132 + d] = rout[e * 128 + d] * inv;
    }
    __syncthreads();
    for (int p = t; p < 256; p += 128) {
        int e = p >> 4, f = p & 15;
        float s = 0.f;
#pragma unroll 8
        for (int k = 0; k < 128; k++) s += sv[e * 132 + k] * sv[f * 132 + k];
        gm[e][f] = s;
    }
    __syncthreads();
    if (t < 16) {
        float s2 = 0.f;
        for (int f = 0; f < 16; f++) {
            float d = gm[t][f] - (t == f ? 1.f : 0.f);
            s2 += d * d;
        }
        float nrm = fmaxf(sqrtf(s2), 1e-12f);
        pen_s[t] = s2 / (nrm * nrm);
    }
    __syncthreads();
    if (t == 0) {
        float s = 0.f;
        for (int e = 0; e < 16; e++) s += pen_s[e];
        g_pen[token] = s;
    }
    for (int e = warp; e < 16; e += 4) {
        float dot = 0.f, ss = 0.f, rs = 0.f;
        for (int d = lane; d < 128; d += 32) {
            float ev = expr[(size_t)token * GH_ + e * 128 + d];
            float rv = sv[e * 132 + d];
            dot += ev * rv; ss += ev * ev; rs += rv * rv;
        }
        dot = wsum(dot); ss = wsum(ss); rs = wsum(rs);
        if (lane == 0) {
            float en = fmaxf(sqrtf(ss), 1e-8f);
            float rn = fmaxf(sqrtf(rs), 1e-8f);
            cosO[token * 16 + e] = 1.f - dot / (en * rn);
        }
    }
}

// -------- penalty mean + load-balance adjustment --------
__global__ void finalize_kernel(const float* __restrict__ ema, float* __restrict__ out) {
    __shared__ float red[256];
    int t = threadIdx.x;
    float s = 0.f;
    for (int i = t; i < NTOK; i += 256) s += g_pen[i];
    red[t] = s; __syncthreads();
    for (int o = 128; o > 0; o >>= 1) { if (t < o) red[t] += red[t + o]; __syncthreads(); }
    if (t == 0) {
        float pen = red[0] / (float)NTOK;
        g_scal[0] = pen;
        out[O_PEN] = pen;
        float tot = 0.f;
        for (int e = 0; e < 16; e++) tot += ema[e];
        for (int e = 0; e < 16; e++) {
            float sc = (tot > 0.f) ? ema[e] / fmaxf(tot, 1e-12f) : 0.f;
            g_scal[1 + e] = sc * 0.01f * 16.f;
        }
    }
}

// -------- top-2 + softmax + adjustment --------
__global__ void topk_kernel(const float* __restrict__ cosv, float* __restrict__ out) {
    int token = blockIdx.x * blockDim.x + threadIdx.x;
    if (token >= NTOK) return;
    float mul = 1.f + g_scal[0];
    float dv[16];
#pragma unroll
    for (int e = 0; e < 16; e++) dv[e] = cosv[token * 16 + e] * mul;
    int i0 = 0; float v0 = dv[0];
#pragma unroll
    for (int e = 1; e < 16; e++) if (dv[e] > v0) { v0 = dv[e]; i0 = e; }
    int i1 = (i0 == 0) ? 1 : 0; float v1 = dv[i1];
#pragma unroll
    for (int e = 0; e < 16; e++) if (e != i0 && dv[e] > v1) { v1 = dv[e]; i1 = e; }
    float e1  = expf(v1 - v0);
    float inv = 1.f / (1.f + e1);
    out[O_MULT + token * 2 + 0] = inv - g_scal[1 + i0];
    out[O_MULT + token * 2 + 1] = e1 * inv - g_scal[1 + i1];
    out[O_SEL + token * 2 + 0] = (float)i0;
    out[O_SEL + token * 2 + 1] = (float)i1;
}

__global__ void wloss_reduce_kernel(float* __restrict__ out) {
    __shared__ float red[256];
    int t = threadIdx.x;
    float s = g_losspart[t];
    red[t] = s; __syncthreads();
    for (int o = 128; o > 0; o >>= 1) { if (t < o) red[t] += red[t + o]; __syncthreads(); }
    if (t == 0) out[O_LOSS] = red[0] / ((float)GH_ * (float)GH_);
}

// -------- host --------
extern "C" void kernel_launch(void* const* d_in, const int* in_sizes, int n_in,
                              void* d_out, int out_size) {
    const float* x      = (const float*)d_in[0];
    const float* hn     = (const float*)d_in[1];
    const float* w_ih   = (const float*)d_in[2];
    const float* w_hh   = (const float*)d_in[3];
    const float* w_expr = (const float*)d_in[4];
    const float* ema    = (const float*)d_in[5];
    float* out = (float*)d_out;

    void* p = 0;
    cudaGetSymbolAddress(&p, g_xi);  float* xi = (float*)p;
    __nv_bfloat16 *xh, *xl, *wih_h, *wih_l, *weT_h, *weT_l;
    cudaGetSymbolAddress(&p, g_xh);    xh = (__nv_bfloat16*)p;
    cudaGetSymbolAddress(&p, g_xl);    xl = (__nv_bfloat16*)p;
    cudaGetSymbolAddress(&p, g_wih_h); wih_h = (__nv_bfloat16*)p;
    cudaGetSymbolAddress(&p, g_wih_l); wih_l = (__nv_bfloat16*)p;
    cudaGetSymbolAddress(&p, g_weT_h); weT_h = (__nv_bfloat16*)p;
    cudaGetSymbolAddress(&p, g_weT_l); weT_l = (__nv_bfloat16*)p;

    static int smem_set = 0;
    if (!smem_set) {
        cudaFuncSetAttribute(mma_gemm_kernel<0>, cudaFuncAttributeMaxDynamicSharedMemorySize, SMTOT);
        cudaFuncSetAttribute(mma_gemm_kernel<1>, cudaFuncAttributeMaxDynamicSharedMemorySize, SMTOT);
        cudaFuncSetAttribute(mma_gemm_kernel<2>, cudaFuncAttributeMaxDynamicSharedMemorySize, SMTOT);
        smem_set = 1;
    }

    init_kernel<<<32, 256>>>(hn);

    split_kernel<<<(NTOK * H_ / 4 + 255) / 256, 256>>>(x, xh, xl, NTOK * H_ / 4);
    split_kernel<<<(G3_ * H_ / 4 + 255) / 256, 256>>>(w_ih, wih_h, wih_l, G3_ * H_ / 4);
    tsplit_kernel<<<dim3(GH_ / 32, H_ / 32), dim3(32, 8)>>>(w_expr, weT_h, weT_l);

    // xi = x @ w_ih^T, stored in PERM layout for the GRU
    mma_gemm_kernel<2><<<dim3(G3_ / 128, NTOK / 128), 256, SMTOT>>>(
        xh, xl, wih_h, wih_l, xi, G3_, H_);
    // expr = x @ w_expr
    mma_gemm_kernel<0><<<dim3(GH_ / 128, NTOK / 128), 256, SMTOT>>>(
        xh, xl, weT_h, weT_l, out + O_EXPR, GH_, H_);

    gru_kernel<<<152, 1024>>>(w_hh, out + O_HN);

    token_kernel<<<NTOK, 128>>>(out + O_EXPR, out + O_COS);
    finalize_kernel<<<1, 256>>>(ema, out);
    topk_kernel<<<8, 256>>>(out + O_COS, out);

    // wloss: W^T W
    mma_gemm_kernel<1><<<dim3(16, 16), 256, SMTOT>>>(
        weT_h, weT_l, weT_h, weT_l, nullptr, GH_, H_);
    wloss_reduce_kernel<<<1, 256>>>(out);
}

// round 15
// speedup vs baseline: 1.0294x; 1.0294x over previous
#include <cuda_runtime.h>
#include <cuda_bf16.h>
#include <math.h>
#include <stdint.h>

// Problem dims
#define B_   4
#define S_   512
#define H_   2048
#define E_   16
#define D_   128
#define GH_  2048
#define G3_  6144
#define NTOK 2048   // B_*S_

// Output layout (flat f32 concat, reference return order)
#define O_MULT 0
#define O_SEL  4096
#define O_EXPR 8192
#define O_HN   4202496
#define O_PEN  4210688
#define O_COS  4210689
#define O_LOSS 4243457

// -------- device scratch --------
__device__ float    g_xi[NTOK * G3_];      // PERM layout: [step][gate][j][b]
__device__ float    g_hs[NTOK * GH_];
__device__ float    g_hbuf[2 * B_ * GH_];
__device__ float    g_pen[NTOK];
__device__ float    g_scal[32];
__device__ float    g_losspart[1024];
__device__ unsigned g_ctr;

// bf16 hi/lo split operands
__device__ __align__(16) __nv_bfloat16 g_xh[NTOK * H_];
__device__ __align__(16) __nv_bfloat16 g_xl[NTOK * H_];
__device__ __align__(16) __nv_bfloat16 g_wih_h[G3_ * H_];
__device__ __align__(16) __nv_bfloat16 g_wih_l[G3_ * H_];
__device__ __align__(16) __nv_bfloat16 g_weT_h[GH_ * H_];
__device__ __align__(16) __nv_bfloat16 g_weT_l[GH_ * H_];

// -------- helpers --------
__device__ __forceinline__ float wsum(float v) {
#pragma unroll
    for (int o = 16; o > 0; o >>= 1) v += __shfl_xor_sync(0xffffffffu, v, o);
    return v;
}
__device__ __forceinline__ uint32_t smem_u32(const void* p) {
    uint32_t a;
    asm("{ .reg .u64 t; cvta.to.shared.u64 t, %1; cvt.u32.u64 %0, t; }"
        : "=r"(a) : "l"(p));
    return a;
}
__device__ __forceinline__ void ldsm4(uint32_t addr, uint32_t* r) {
    asm volatile("ldmatrix.sync.aligned.m8n8.x4.shared.b16 {%0,%1,%2,%3}, [%4];"
                 : "=r"(r[0]), "=r"(r[1]), "=r"(r[2]), "=r"(r[3]) : "r"(addr));
}
__device__ __forceinline__ void mma16816(float* c, const uint32_t* a,
                                         uint32_t b0, uint32_t b1) {
    asm volatile(
        "mma.sync.aligned.m16n8k16.row.col.f32.bf16.bf16.f32 "
        "{%0,%1,%2,%3}, {%4,%5,%6,%7}, {%8,%9}, {%0,%1,%2,%3};"
        : "+f"(c[0]), "+f"(c[1]), "+f"(c[2]), "+f"(c[3])
        : "r"(a[0]), "r"(a[1]), "r"(a[2]), "r"(a[3]), "r"(b0), "r"(b1));
}
__device__ __forceinline__ void cpa16(uint32_t s, const void* g) {
    asm volatile("cp.async.cg.shared.global [%0], [%1], 16;" :: "r"(s), "l"(g));
}
__device__ __forceinline__ void cpa_commit() {
    asm volatile("cp.async.commit_group;");
}
template <int N>
__device__ __forceinline__ void cpa_wait() {
    asm volatile("cp.async.wait_group %0;" :: "n"(N));
}
// R8-proven atomic-counter grid barrier (exact).
__device__ __forceinline__ void gsync(unsigned target) {
    __threadfence();
    __syncthreads();
    if (threadIdx.x == 0) {
        atomicAdd(&g_ctr, 1u);
        volatile unsigned* p = &g_ctr;
        while (*p < target) { __nanosleep(32); }
    }
    __syncthreads();
}

// -------- init --------
__global__ void init_kernel(const float* __restrict__ hn) {
    int i = blockIdx.x * 256 + threadIdx.x;
    if (i == 0) g_ctr = 0u;
    if (i < B_ * GH_) g_hbuf[i] = hn[i];
}

// -------- split f32 -> bf16 hi/lo --------
__global__ void split_kernel(const float* __restrict__ src,
                             __nv_bfloat16* __restrict__ hi,
                             __nv_bfloat16* __restrict__ lo, int n4) {
    int i = blockIdx.x * 256 + threadIdx.x;
    if (i >= n4) return;
    float4 v = reinterpret_cast<const float4*>(src)[i];
    __nv_bfloat16 h0 = __float2bfloat16(v.x), h1 = __float2bfloat16(v.y);
    __nv_bfloat16 h2 = __float2bfloat16(v.z), h3 = __float2bfloat16(v.w);
    __nv_bfloat16 l0 = __float2bfloat16(v.x - __bfloat162float(h0));
    __nv_bfloat16 l1 = __float2bfloat16(v.y - __bfloat162float(h1));
    __nv_bfloat16 l2 = __float2bfloat16(v.z - __bfloat162float(h2));
    __nv_bfloat16 l3 = __float2bfloat16(v.w - __bfloat162float(h3));
    reinterpret_cast<__nv_bfloat162*>(hi)[2 * i]     = __nv_bfloat162(h0, h1);
    reinterpret_cast<__nv_bfloat162*>(hi)[2 * i + 1] = __nv_bfloat162(h2, h3);
    reinterpret_cast<__nv_bfloat162*>(lo)[2 * i]     = __nv_bfloat162(l0, l1);
    reinterpret_cast<__nv_bfloat162*>(lo)[2 * i + 1] = __nv_bfloat162(l2, l3);
}

// -------- transpose + split: W[H,GH] -> T[GH,H] bf16 hi/lo --------
__global__ void tsplit_kernel(const float* __restrict__ W,
                              __nv_bfloat16* __restrict__ Th,
                              __nv_bfloat16* __restrict__ Tl) {
    __shared__ float t[32][33];
    int gc = blockIdx.x * 32;
    int gr = blockIdx.y * 32;
    int tx = threadIdx.x, ty = threadIdx.y;
#pragma unroll
    for (int r = 0; r < 32; r += 8)
        t[ty + r][tx] = W[(size_t)(gr + ty + r) * GH_ + gc + tx];
    __syncthreads();
#pragma unroll
    for (int r = 0; r < 32; r += 8) {
        float v = t[tx][ty + r];
        __nv_bfloat16 h = __float2bfloat16(v);
        __nv_bfloat16 l = __float2bfloat16(v - __bfloat162float(h));
        size_t o = (size_t)(gc + ty + r) * H_ + gr + tx;
        Th[o] = h; Tl[o] = l;
    }
}

// ========== mma.sync GEMM: C[M,N] = A @ B^T, bf16 hi/lo 3-term split =====
#define ROWB  80
#define TILEB (128 * ROWB)       // 10240
#define BUFB  (4 * TILEB)        // 40960
#define SMTOT (2 * BUFB)         // 81920

template <int EPI>
__global__ void __launch_bounds__(256) mma_gemm_kernel(
    const __nv_bfloat16* __restrict__ Ah, const __nv_bfloat16* __restrict__ Al,
    const __nv_bfloat16* __restrict__ Bh, const __nv_bfloat16* __restrict__ Bl,
    float* __restrict__ C, int N, int K)
{
    extern __shared__ char smem[];
    const uint32_t sb = smem_u32(smem);
    const int t    = threadIdx.x;
    const int lane = t & 31;
    const int w    = t >> 5;
    const int wm   = w >> 1;
    const int wn   = w & 1;
    const int n0   = blockIdx.x * 128;
    const int m0   = blockIdx.y * 128;

    const __nv_bfloat16* srcs[4] = {
        Ah + (size_t)m0 * K, Al + (size_t)m0 * K,
        Bh + (size_t)n0 * K, Bl + (size_t)n0 * K };

    const int srow0 = t >> 2;
    const int srow1 = srow0 + 64;
    const int sc16  = t & 3;

    float acc[2][8][4];
#pragma unroll
    for (int i = 0; i < 2; i++)
#pragma unroll
        for (int j = 0; j < 8; j++)
#pragma unroll
            for (int c = 0; c < 4; c++) acc[i][j][c] = 0.f;

    const uint32_t a_row = wm * 32 + (lane & 15);
    const uint32_t a_cs  = lane >> 4;
    const uint32_t b_row = wn * 64 + ((lane >> 4) << 3) + (lane & 7);
    const uint32_t b_cs  = (lane >> 3) & 1;

    const int NCH = K >> 5;

    auto stage = [&](int ch, int buf) {
        const uint32_t bb = sb + buf * BUFB;
        const int koff = ch * 32 + sc16 * 8;
#pragma unroll
        for (int o = 0; o < 4; o++) {
            cpa16(bb + o * TILEB + srow0 * ROWB + sc16 * 16,
                  srcs[o] + (size_t)srow0 * K + koff);
            cpa16(bb + o * TILEB + srow1 * ROWB + sc16 * 16,
                  srcs[o] + (size_t)srow1 * K + koff);
        }
        cpa_commit();
    };

    stage(0, 0);
#pragma unroll 1
    for (int ch = 0; ch < NCH; ch++) {
        const int buf = ch & 1;
        if (ch + 1 < NCH) { stage(ch + 1, buf ^ 1); cpa_wait<1>(); }
        else              { cpa_wait<0>(); }
        __syncthreads();

        const uint32_t bb = sb + buf * BUFB;
#pragma unroll
        for (int kt = 0; kt < 2; kt++) {
            uint32_t ah[2][4], al[2][4], bhf[4][4], blf[4][4];
#pragma unroll
            for (int mt = 0; mt < 2; mt++) {
                uint32_t off = bb + (a_row + mt * 16) * ROWB + (kt * 2 + a_cs) * 16;
                ldsm4(off, ah[mt]);
                ldsm4(off + TILEB, al[mt]);
            }
#pragma unroll
            for (int ntp = 0; ntp < 4; ntp++) {
                uint32_t off = bb + 2 * TILEB + (b_row + ntp * 16) * ROWB + (kt * 2 + b_cs) * 16;
                ldsm4(off, bhf[ntp]);
                ldsm4(off + TILEB, blf[ntp]);
            }
#pragma unroll
            for (int mt = 0; mt < 2; mt++)
#pragma unroll
                for (int ntp = 0; ntp < 4; ntp++) {
                    mma16816(acc[mt][2 * ntp],     ah[mt], bhf[ntp][0], bhf[ntp][1]);
                    mma16816(acc[mt][2 * ntp + 1], ah[mt], bhf[ntp][2], bhf[ntp][3]);
                }
#pragma unroll
            for (int mt = 0; mt < 2; mt++)
#pragma unroll
                for (int ntp = 0; ntp < 4; ntp++) {
                    mma16816(acc[mt][2 * ntp],     ah[mt], blf[ntp][0], blf[ntp][1]);
                    mma16816(acc[mt][2 * ntp + 1], ah[mt], blf[ntp][2], blf[ntp][3]);
                }
#pragma unroll
            for (int mt = 0; mt < 2; mt++)
#pragma unroll
                for (int ntp = 0; ntp < 4; ntp++) {
                    mma16816(acc[mt][2 * ntp],     al[mt], bhf[ntp][0], bhf[ntp][1]);
                    mma16816(acc[mt][2 * ntp + 1], al[mt], bhf[ntp][2], bhf[ntp][3]);
                }
        }
        __syncthreads();
    }

    const int g  = lane >> 2;
    const int t2 = lane & 3;
    if (EPI == 0) {
#pragma unroll
        for (int mt = 0; mt < 2; mt++) {
            int row = m0 + wm * 32 + mt * 16 + g;
#pragma unroll
            for (int nt = 0; nt < 8; nt++) {
                int col = n0 + wn * 64 + nt * 8 + t2 * 2;
                *reinterpret_cast<float2*>(&C[(size_t)row * N + col]) =
                    make_float2(acc[mt][nt][0], acc[mt][nt][1]);
                *reinterpret_cast<float2*>(&C[(size_t)(row + 8) * N + col]) =
                    make_float2(acc[mt][nt][2], acc[mt][nt][3]);
            }
        }
    } else if (EPI == 2) {
        // xi PERM store: dst ((step*3+gate)*GH+j)*4+b
#pragma unroll
        for (int mt = 0; mt < 2; mt++) {
#pragma unroll
            for (int rr = 0; rr < 2; rr++) {
                int row  = m0 + wm * 32 + mt * 16 + g + rr * 8;
                int b    = row >> 9;
                int st   = row & 511;
#pragma unroll
                for (int nt = 0; nt < 8; nt++) {
                    int col  = n0 + wn * 64 + nt * 8 + t2 * 2;
                    int gate = col >> 11;
                    int j    = col & 2047;
                    size_t base = ((size_t)(st * 3 + gate) * GH_ + j) * 4 + b;
                    C[base]     = acc[mt][nt][rr * 2 + 0];
                    C[base + 4] = acc[mt][nt][rr * 2 + 1];
                }
            }
        }
    } else {
        float s = 0.f;
#pragma unroll
        for (int mt = 0; mt < 2; mt++) {
            int row = m0 + wm * 32 + mt * 16 + g;
#pragma unroll
            for (int nt = 0; nt < 8; nt++) {
                int col = n0 + wn * 64 + nt * 8 + t2 * 2;
                float d0 = acc[mt][nt][0] - (row == col ? 1.f : 0.f);
                float d1 = acc[mt][nt][1] - (row == col + 1 ? 1.f : 0.f);
                float d2 = acc[mt][nt][2] - (row + 8 == col ? 1.f : 0.f);
                float d3 = acc[mt][nt][3] - (row + 8 == col + 1 ? 1.f : 0.f);
                s += d0 * d0 + d1 * d1 + d2 * d2 + d3 * d3;
            }
        }
        float* red = reinterpret_cast<float*>(smem);
        red[t] = s; __syncthreads();
        for (int o = 128; o > 0; o >>= 1) { if (t < o) red[t] += red[t + o]; __syncthreads(); }
        if (t == 0) g_losspart[blockIdx.y * gridDim.x + blockIdx.x] = red[0];
    }
}

// ===== persistent GRU: grid 152, 1024 thr, split-K=2, SoA h (R8 EXACT) =====
__global__ void __launch_bounds__(1024) gru_kernel(const float* __restrict__ w_hh,
                                                   float* __restrict__ out_hn) {
    __shared__ float h_s[4][GH_];     // SoA: [batch][k] -> conflict-free float4 LDS
    __shared__ float part[16][12];
    const int t    = threadIdx.x;
    const int lane = t & 31;
    const int warp = t >> 5;          // 0..31
    const int pair = warp >> 1;       // 0..15
    const int half = warp & 1;
    const int nb   = gridDim.x;
    const int j    = pair * 152 + blockIdx.x;
    const bool valid = (j < GH_);
    unsigned target = 0;

    const float* wr = w_hh + (size_t)j * GH_;
    const float* wz = w_hh + (size_t)(GH_ + j) * GH_;
    const float* wn = w_hh + (size_t)(2 * GH_ + j) * GH_;
    const int kbase = half * 1024 + lane * 4;

    for (int step = 0; step < S_; step++) {
        if (step > 0) { target += nb; gsync(target); }
        const float* hsrc = g_hbuf + (step & 1) * (B_ * GH_);
        // SoA staging: thread t handles float4 index t (512 per batch)
        if (t < 512) {
#pragma unroll
            for (int b = 0; b < 4; b++) {
                float4 v = __ldcg(reinterpret_cast<const float4*>(hsrc + b * GH_) + t);
                *reinterpret_cast<float4*>(&h_s[b][t * 4]) = v;
            }
        }
        __syncthreads();
        float* hdst = g_hbuf + ((step + 1) & 1) * (B_ * GH_);

        float4 ar = make_float4(0.f, 0.f, 0.f, 0.f);
        float4 az = ar, an = ar;
        float xiv = 0.f;
        if (valid) {
            if (half == 0 && lane < 12)
                xiv = __ldcg(g_xi + ((size_t)(step * 3 + (lane >> 2)) * GH_ + j) * 4 + (lane & 3));

#pragma unroll
            for (int it = 0; it < 8; it++) {
                const int k = kbase + it * 128;
                float4 r4 = __ldcg(reinterpret_cast<const float4*>(wr + k));
                float4 z4 = __ldcg(reinterpret_cast<const float4*>(wz + k));
                float4 n4 = __ldcg(reinterpret_cast<const float4*>(wn + k));
                float4 hb0 = *reinterpret_cast<const float4*>(&h_s[0][k]);
                float4 hb1 = *reinterpret_cast<const float4*>(&h_s[1][k]);
                float4 hb2 = *reinterpret_cast<const float4*>(&h_s[2][k]);
                float4 hb3 = *reinterpret_cast<const float4*>(&h_s[3][k]);
                ar.x += r4.x*hb0.x + r4.y*hb0.y + r4.z*hb0.z + r4.w*hb0.w;
                ar.y += r4.x*hb1.x + r4.y*hb1.y + r4.z*hb1.z + r4.w*hb1.w;
                ar.z += r4.x*hb2.x + r4.y*hb2.y + r4.z*hb2.z + r4.w*hb2.w;
                ar.w += r4.x*hb3.x + r4.y*hb3.y + r4.z*hb3.z + r4.w*hb3.w;
                az.x += z4.x*hb0.x + z4.y*hb0.y + z4.z*hb0.z + z4.w*hb0.w;
                az.y += z4.x*hb1.x + z4.y*hb1.y + z4.z*hb1.z + z4.w*hb1.w;
                az.z += z4.x*hb2.x + z4.y*hb2.y + z4.z*hb2.z + z4.w*hb2.w;
                az.w += z4.x*hb3.x + z4.y*hb3.y + z4.z*hb3.z + z4.w*hb3.w;
                an.x += n4.x*hb0.x + n4.y*hb0.y + n4.z*hb0.z + n4.w*hb0.w;
                an.y += n4.x*hb1.x + n4.y*hb1.y + n4.z*hb1.z + n4.w*hb1.w;
                an.z += n4.x*hb2.x + n4.y*hb2.y + n4.z*hb2.z + n4.w*hb2.w;
                an.w += n4.x*hb3.x + n4.y*hb3.y + n4.z*hb3.z + n4.w*hb3.w;
            }

            ar.x = wsum(ar.x); ar.y = wsum(ar.y); ar.z = wsum(ar.z); ar.w = wsum(ar.w);
            az.x = wsum(az.x); az.y = wsum(az.y); az.z = wsum(az.z); az.w = wsum(az.w);
            an.x = wsum(an.x); an.y = wsum(an.y); an.z = wsum(an.z); an.w = wsum(an.w);
            if (half == 1 && lane == 0) {
                part[pair][0]  = ar.x; part[pair][1]  = ar.y;
                part[pair][2]  = ar.z; part[pair][3]  = ar.w;
                part[pair][4]  = az.x; part[pair][5]  = az.y;
                part[pair][6]  = az.z; part[pair][7]  = az.w;
                part[pair][8]  = an.x; part[pair][9]  = an.y;
                part[pair][10] = an.z; part[pair][11] = an.w;
            }
        }
        __syncthreads();
        if (valid && half == 0) {
            int b = lane & 3;
            float xr = __shfl_sync(0xffffffffu, xiv, b);
            float xz = __shfl_sync(0xffffffffu, xiv, 4 + b);
            float xn = __shfl_sync(0xffffffffu, xiv, 8 + b);
            if (lane < 4) {
                float arb = ((b & 1) ? ((b & 2) ? ar.w : ar.y) : ((b & 2) ? ar.z : ar.x))
                            + part[pair][b];
                float azb = ((b & 1) ? ((b & 2) ? az.w : az.y) : ((b & 2) ? az.z : az.x))
                            + part[pair][4 + b];
                float anb = ((b & 1) ? ((b & 2) ? an.w : an.y) : ((b & 2) ? an.z : an.x))
                            + part[pair][8 + b];
                float hob = h_s[b][j];
                float r = 1.f / (1.f + expf(-(xr + arb)));
                float z = 1.f / (1.f + expf(-(xz + azb)));
                float n = tanhf(xn + r * anb);
                float hv = (1.f - z) * n + z * hob;
                __stcg(hdst + b * GH_ + j, hv);
                __stcg(g_hs + (size_t)(b * S_ + step) * GH_ + j, hv);
            }
        }
    }
    target += nb; gsync(target);
    if (blockIdx.x == 0) {
        const float* hf = g_hbuf;   // 512 steps even -> buffer 0
        for (int i = t; i < B_ * GH_; i += 1024) out_hn[i] = __ldcg(hf + i);
    }
}

// -------- per-token: normalize rout, gram penalty, cosine sims --------
__global__ void __launch_bounds__(128) token_kernel(const float* __restrict__ expr,
                                                    float* __restrict__ cosO) {
    const int token = blockIdx.x;
    const int t = threadIdx.x, lane = t & 31, warp = t >> 5;
    __shared__ float sv[16 * 132];
    __shared__ float gm[16][17];
    __shared__ float pen_s[16];
    const float* rout = g_hs + (size_t)token * GH_;

    for (int e = warp; e < 16; e += 4) {
        float s = 0.f;
        for (int d = lane; d < 128; d += 32) { float v = rout[e * 128 + d]; s += v * v; }
        s = wsum(s);
        float inv = 1.f / fmaxf(sqrtf(s), 1e-12f);
        for (int d = lane; d < 128; d += 32) sv[e * 132 + d] = rout[e * 128 + d] * inv;
    }
    __syncthreads();
    for (int p = t; p < 256; p += 128) {
        int e = p >> 4, f = p & 15;
        float s = 0.f;
#pragma unroll 8
        for (int k = 0; k < 128; k++) s += sv[e * 132 + k] * sv[f * 132 + k];
        gm[e][f] = s;
    }
    __syncthreads();
    if (t < 16) {
        float s2 = 0.f;
        for (int f = 0; f < 16; f++) {
            float d = gm[t][f] - (t == f ? 1.f : 0.f);
            s2 += d * d;
        }
        float nrm = fmaxf(sqrtf(s2), 1e-12f);
        pen_s[t] = s2 / (nrm * nrm);
    }
    __syncthreads();
    if (t == 0) {
        float s = 0.f;
        for (int e = 0; e < 16; e++) s += pen_s[e];
        g_pen[token] = s;
    }
    for (int e = warp; e < 16; e += 4) {
        float dot = 0.f, ss = 0.f, rs = 0.f;
        for (int d = lane; d < 128; d += 32) {
            float ev = expr[(size_t)token * GH_ + e * 128 + d];
            float rv = sv[e * 132 + d];
            dot += ev * rv; ss += ev * ev; rs += rv * rv;
        }
        dot = wsum(dot); ss = wsum(ss); rs = wsum(rs);
        if (lane == 0) {
            float en = fmaxf(sqrtf(ss), 1e-8f);
            float rn = fmaxf(sqrtf(rs), 1e-8f);
            cosO[token * 16 + e] = 1.f - dot / (en * rn);
        }
    }
}

// -------- penalty mean + load-balance adjustment --------
__global__ void finalize_kernel(const float* __restrict__ ema, float* __restrict__ out) {
    __shared__ float red[256];
    int t = threadIdx.x;
    float s = 0.f;
    for (int i = t; i < NTOK; i += 256) s += g_pen[i];
    red[t] = s; __syncthreads();
    for (int o = 128; o > 0; o >>= 1) { if (t < o) red[t] += red[t + o]; __syncthreads(); }
    if (t == 0) {
        float pen = red[0] / (float)NTOK;
        g_scal[0] = pen;
        out[O_PEN] = pen;
        float tot = 0.f;
        for (int e = 0; e < 16; e++) tot += ema[e];
        for (int e = 0; e < 16; e++) {
            float sc = (tot > 0.f) ? ema[e] / fmaxf(tot, 1e-12f) : 0.f;
            g_scal[1 + e] = sc * 0.01f * 16.f;
        }
    }
}

// -------- top-2 + softmax + adjustment --------
__global__ void topk_kernel(const float* __restrict__ cosv, float* __restrict__ out) {
    int token = blockIdx.x * blockDim.x + threadIdx.x;
    if (token >= NTOK) return;
    float mul = 1.f + g_scal[0];
    float dv[16];
#pragma unroll
    for (int e = 0; e < 16; e++) dv[e] = cosv[token * 16 + e] * mul;
    int i0 = 0; float v0 = dv[0];
#pragma unroll
    for (int e = 1; e < 16; e++) if (dv[e] > v0) { v0 = dv[e]; i0 = e; }
    int i1 = (i0 == 0) ? 1 : 0; float v1 = dv[i1];
#pragma unroll
    for (int e = 0; e < 16; e++) if (e != i0 && dv[e] > v1) { v1 = dv[e]; i1 = e; }
    float e1  = expf(v1 - v0);
    float inv = 1.f / (1.f + e1);
    out[O_MULT + token * 2 + 0] = inv - g_scal[1 + i0];
    out[O_MULT + token * 2 + 1] = e1 * inv - g_scal[1 + i1];
    out[O_SEL + token * 2 + 0] = (float)i0;
    out[O_SEL + token * 2 + 1] = (float)i1;
}

__global__ void wloss_reduce_kernel(float* __restrict__ out) {
    __shared__ float red[256];
    int t = threadIdx.x;
    float s = g_losspart[t];
    red[t] = s; __syncthreads();
    for (int o = 128; o > 0; o >>= 1) { if (t < o) red[t] += red[t + o]; __syncthreads(); }
    if (t == 0) out[O_LOSS] = red[0] / ((float)GH_ * (float)GH_);
}

// -------- host --------
extern "C" void kernel_launch(void* const* d_in, const int* in_sizes, int n_in,
                              void* d_out, int out_size) {
    const float* x      = (const float*)d_in[0];
    const float* hn     = (const float*)d_in[1];
    const float* w_ih   = (const float*)d_in[2];
    const float* w_hh   = (const float*)d_in[3];
    const float* w_expr = (const float*)d_in[4];
    const float* ema    = (const float*)d_in[5];
    float* out = (float*)d_out;

    void* p = 0;
    cudaGetSymbolAddress(&p, g_xi);  float* xi = (float*)p;
    __nv_bfloat16 *xh, *xl, *wih_h, *wih_l, *weT_h, *weT_l;
    cudaGetSymbolAddress(&p, g_xh);    xh = (__nv_bfloat16*)p;
    cudaGetSymbolAddress(&p, g_xl);    xl = (__nv_bfloat16*)p;
    cudaGetSymbolAddress(&p, g_wih_h); wih_h = (__nv_bfloat16*)p;
    cudaGetSymbolAddress(&p, g_wih_l); wih_l = (__nv_bfloat16*)p;
    cudaGetSymbolAddress(&p, g_weT_h); weT_h = (__nv_bfloat16*)p;
    cudaGetSymbolAddress(&p, g_weT_l); weT_l = (__nv_bfloat16*)p;

    static int smem_set = 0;
    if (!smem_set) {
        cudaFuncSetAttribute(mma_gemm_kernel<0>, cudaFuncAttributeMaxDynamicSharedMemorySize, SMTOT);
        cudaFuncSetAttribute(mma_gemm_kernel<1>, cudaFuncAttributeMaxDynamicSharedMemorySize, SMTOT);
        cudaFuncSetAttribute(mma_gemm_kernel<2>, cudaFuncAttributeMaxDynamicSharedMemorySize, SMTOT);
        smem_set = 1;
    }

    init_kernel<<<32, 256>>>(hn);

    split_kernel<<<(NTOK * H_ / 4 + 255) / 256, 256>>>(x, xh, xl, NTOK * H_ / 4);
    split_kernel<<<(G3_ * H_ / 4 + 255) / 256, 256>>>(w_ih, wih_h, wih_l, G3_ * H_ / 4);
    tsplit_kernel<<<dim3(GH_ / 32, H_ / 32), dim3(32, 8)>>>(w_expr, weT_h, weT_l);

    // xi = x @ w_ih^T, stored in PERM layout for the GRU
    mma_gemm_kernel<2><<<dim3(G3_ / 128, NTOK / 128), 256, SMTOT>>>(
        xh, xl, wih_h, wih_l, xi, G3_, H_);
    // expr = x @ w_expr
    mma_gemm_kernel<0><<<dim3(GH_ / 128, NTOK / 128), 256, SMTOT>>>(
        xh, xl, weT_h, weT_l, out + O_EXPR, GH_, H_);

    gru_kernel<<<152, 1024>>>(w_hh, out + O_HN);

    token_kernel<<<NTOK, 128>>>(out + O_EXPR, out + O_COS);
    finalize_kernel<<<1, 256>>>(ema, out);
    topk_kernel<<<8, 256>>>(out + O_COS, out);

    // wloss: W^T W
    mma_gemm_kernel<1><<<dim3(16, 16), 256, SMTOT>>>(
        weT_h, weT_l, weT_h, weT_l, nullptr, GH_, H_);
    wloss_reduce_kernel<<<1, 256>>>(out);
}

// round 16
// speedup vs baseline: 1.0496x; 1.0196x over previous
#include <cuda_runtime.h>
#include <cuda_bf16.h>
#include <math.h>
#include <stdint.h>

// Problem dims
#define B_   4
#define S_   512
#define H_   2048
#define E_   16
#define D_   128
#define GH_  2048
#define G3_  6144
#define NTOK 2048   // B_*S_

// Output layout (flat f32 concat, reference return order)
#define O_MULT 0
#define O_SEL  4096
#define O_EXPR 8192
#define O_HN   4202496
#define O_PEN  4210688
#define O_COS  4210689
#define O_LOSS 4243457

// -------- device scratch --------
__device__ float    g_xi[NTOK * G3_];      // PERM layout: [step][gate][j][b]
__device__ float    g_hs[NTOK * GH_];
__device__ float    g_hbuf[2 * B_ * GH_];
__device__ float    g_pen[NTOK];
__device__ float    g_scal[32];
__device__ float    g_losspart[1024];
__device__ unsigned g_ctr;

// bf16 hi/lo split operands
__device__ __align__(16) __nv_bfloat16 g_xh[NTOK * H_];
__device__ __align__(16) __nv_bfloat16 g_xl[NTOK * H_];
__device__ __align__(16) __nv_bfloat16 g_wih_h[G3_ * H_];
__device__ __align__(16) __nv_bfloat16 g_wih_l[G3_ * H_];
__device__ __align__(16) __nv_bfloat16 g_weT_h[GH_ * H_];
__device__ __align__(16) __nv_bfloat16 g_weT_l[GH_ * H_];

// -------- helpers --------
__device__ __forceinline__ float wsum(float v) {
#pragma unroll
    for (int o = 16; o > 0; o >>= 1) v += __shfl_xor_sync(0xffffffffu, v, o);
    return v;
}
__device__ __forceinline__ uint32_t smem_u32(const void* p) {
    uint32_t a;
    asm("{ .reg .u64 t; cvta.to.shared.u64 t, %1; cvt.u32.u64 %0, t; }"
        : "=r"(a) : "l"(p));
    return a;
}
__device__ __forceinline__ void ldsm4(uint32_t addr, uint32_t* r) {
    asm volatile("ldmatrix.sync.aligned.m8n8.x4.shared.b16 {%0,%1,%2,%3}, [%4];"
                 : "=r"(r[0]), "=r"(r[1]), "=r"(r[2]), "=r"(r[3]) : "r"(addr));
}
__device__ __forceinline__ void mma16816(float* c, const uint32_t* a,
                                         uint32_t b0, uint32_t b1) {
    asm volatile(
        "mma.sync.aligned.m16n8k16.row.col.f32.bf16.bf16.f32 "
        "{%0,%1,%2,%3}, {%4,%5,%6,%7}, {%8,%9}, {%0,%1,%2,%3};"
        : "+f"(c[0]), "+f"(c[1]), "+f"(c[2]), "+f"(c[3])
        : "r"(a[0]), "r"(a[1]), "r"(a[2]), "r"(a[3]), "r"(b0), "r"(b1));
}
__device__ __forceinline__ void cpa16(uint32_t s, const void* g) {
    asm volatile("cp.async.cg.shared.global [%0], [%1], 16;" :: "r"(s), "l"(g));
}
__device__ __forceinline__ void cpa_commit() {
    asm volatile("cp.async.commit_group;");
}
template <int N>
__device__ __forceinline__ void cpa_wait() {
    asm volatile("cp.async.wait_group %0;" :: "n"(N));
}
// R8-proven atomic-counter grid barrier (exact).
__device__ __forceinline__ void gsync(unsigned target) {
    __threadfence();
    __syncthreads();
    if (threadIdx.x == 0) {
        atomicAdd(&g_ctr, 1u);
        volatile unsigned* p = &g_ctr;
        while (*p < target) { __nanosleep(32); }
    }
    __syncthreads();
}

// -------- init --------
__global__ void init_kernel(const float* __restrict__ hn) {
    int i = blockIdx.x * 256 + threadIdx.x;
    if (i == 0) g_ctr = 0u;
    if (i < B_ * GH_) g_hbuf[i] = hn[i];
}

// -------- split f32 -> bf16 hi/lo --------
__global__ void split_kernel(const float* __restrict__ src,
                             __nv_bfloat16* __restrict__ hi,
                             __nv_bfloat16* __restrict__ lo, int n4) {
    int i = blockIdx.x * 256 + threadIdx.x;
    if (i >= n4) return;
    float4 v = reinterpret_cast<const float4*>(src)[i];
    __nv_bfloat16 h0 = __float2bfloat16(v.x), h1 = __float2bfloat16(v.y);
    __nv_bfloat16 h2 = __float2bfloat16(v.z), h3 = __float2bfloat16(v.w);
    __nv_bfloat16 l0 = __float2bfloat16(v.x - __bfloat162float(h0));
    __nv_bfloat16 l1 = __float2bfloat16(v.y - __bfloat162float(h1));
    __nv_bfloat16 l2 = __float2bfloat16(v.z - __bfloat162float(h2));
    __nv_bfloat16 l3 = __float2bfloat16(v.w - __bfloat162float(h3));
    reinterpret_cast<__nv_bfloat162*>(hi)[2 * i]     = __nv_bfloat162(h0, h1);
    reinterpret_cast<__nv_bfloat162*>(hi)[2 * i + 1] = __nv_bfloat162(h2, h3);
    reinterpret_cast<__nv_bfloat162*>(lo)[2 * i]     = __nv_bfloat162(l0, l1);
    reinterpret_cast<__nv_bfloat162*>(lo)[2 * i + 1] = __nv_bfloat162(l2, l3);
}

// -------- transpose + split: W[H,GH] -> T[GH,H] bf16 hi/lo --------
__global__ void tsplit_kernel(const float* __restrict__ W,
                              __nv_bfloat16* __restrict__ Th,
                              __nv_bfloat16* __restrict__ Tl) {
    __shared__ float t[32][33];
    int gc = blockIdx.x * 32;
    int gr = blockIdx.y * 32;
    int tx = threadIdx.x, ty = threadIdx.y;
#pragma unroll
    for (int r = 0; r < 32; r += 8)
        t[ty + r][tx] = W[(size_t)(gr + ty + r) * GH_ + gc + tx];
    __syncthreads();
#pragma unroll
    for (int r = 0; r < 32; r += 8) {
        float v = t[tx][ty + r];
        __nv_bfloat16 h = __float2bfloat16(v);
        __nv_bfloat16 l = __float2bfloat16(v - __bfloat162float(h));
        size_t o = (size_t)(gc + ty + r) * H_ + gr + tx;
        Th[o] = h; Tl[o] = l;
    }
}

// ========== mma.sync GEMM: C[M,N] = A @ B^T, bf16 hi/lo 3-term split =====
// EPI==0: store C.  EPI==1: wloss upper-triangle tile, weighted sum((C-I)^2).
// EPI==2: store xi PERM layout.
#define ROWB  80
#define TILEB (128 * ROWB)       // 10240
#define BUFB  (4 * TILEB)        // 40960
#define SMTOT (2 * BUFB)         // 81920

template <int EPI>
__global__ void __launch_bounds__(256) mma_gemm_kernel(
    const __nv_bfloat16* __restrict__ Ah, const __nv_bfloat16* __restrict__ Al,
    const __nv_bfloat16* __restrict__ Bh, const __nv_bfloat16* __restrict__ Bl,
    float* __restrict__ C, int N, int K)
{
    extern __shared__ char smem[];
    const uint32_t sb = smem_u32(smem);
    const int t    = threadIdx.x;
    const int lane = t & 31;
    const int w    = t >> 5;
    const int wm   = w >> 1;
    const int wn   = w & 1;

    int tile_x = blockIdx.x, tile_y = blockIdx.y;
    if (EPI == 1) {
        // upper-triangle tile map: bid -> (ty, tx), tx >= ty, 16x16 tiles
        int rem = blockIdx.x, r = 0;
        while (rem >= 16 - r) { rem -= 16 - r; r++; }
        tile_y = r; tile_x = r + rem;
    }
    const int n0 = tile_x * 128;
    const int m0 = tile_y * 128;

    const __nv_bfloat16* srcs[4] = {
        Ah + (size_t)m0 * K, Al + (size_t)m0 * K,
        Bh + (size_t)n0 * K, Bl + (size_t)n0 * K };

    const int srow0 = t >> 2;
    const int srow1 = srow0 + 64;
    const int sc16  = t & 3;

    float acc[2][8][4];
#pragma unroll
    for (int i = 0; i < 2; i++)
#pragma unroll
        for (int j = 0; j < 8; j++)
#pragma unroll
            for (int c = 0; c < 4; c++) acc[i][j][c] = 0.f;

    const uint32_t a_row = wm * 32 + (lane & 15);
    const uint32_t a_cs  = lane >> 4;
    const uint32_t b_row = wn * 64 + ((lane >> 4) << 3) + (lane & 7);
    const uint32_t b_cs  = (lane >> 3) & 1;

    const int NCH = K >> 5;

    auto stage = [&](int ch, int buf) {
        const uint32_t bb = sb + buf * BUFB;
        const int koff = ch * 32 + sc16 * 8;
#pragma unroll
        for (int o = 0; o < 4; o++) {
            cpa16(bb + o * TILEB + srow0 * ROWB + sc16 * 16,
                  srcs[o] + (size_t)srow0 * K + koff);
            cpa16(bb + o * TILEB + srow1 * ROWB + sc16 * 16,
                  srcs[o] + (size_t)srow1 * K + koff);
        }
        cpa_commit();
    };

    stage(0, 0);
#pragma unroll 1
    for (int ch = 0; ch < NCH; ch++) {
        const int buf = ch & 1;
        if (ch + 1 < NCH) { stage(ch + 1, buf ^ 1); cpa_wait<1>(); }
        else              { cpa_wait<0>(); }
        __syncthreads();

        const uint32_t bb = sb + buf * BUFB;
#pragma unroll
        for (int kt = 0; kt < 2; kt++) {
            uint32_t ah[2][4], al[2][4], bhf[4][4], blf[4][4];
#pragma unroll
            for (int mt = 0; mt < 2; mt++) {
                uint32_t off = bb + (a_row + mt * 16) * ROWB + (kt * 2 + a_cs) * 16;
                ldsm4(off, ah[mt]);
                ldsm4(off + TILEB, al[mt]);
            }
#pragma unroll
            for (int ntp = 0; ntp < 4; ntp++) {
                uint32_t off = bb + 2 * TILEB + (b_row + ntp * 16) * ROWB + (kt * 2 + b_cs) * 16;
                ldsm4(off, bhf[ntp]);
                ldsm4(off + TILEB, blf[ntp]);
            }
#pragma unroll
            for (int mt = 0; mt < 2; mt++)
#pragma unroll
                for (int ntp = 0; ntp < 4; ntp++) {
                    mma16816(acc[mt][2 * ntp],     ah[mt], bhf[ntp][0], bhf[ntp][1]);
                    mma16816(acc[mt][2 * ntp + 1], ah[mt], bhf[ntp][2], bhf[ntp][3]);
                }
#pragma unroll
            for (int mt = 0; mt < 2; mt++)
#pragma unroll
                for (int ntp = 0; ntp < 4; ntp++) {
                    mma16816(acc[mt][2 * ntp],     ah[mt], blf[ntp][0], blf[ntp][1]);
                    mma16816(acc[mt][2 * ntp + 1], ah[mt], blf[ntp][2], blf[ntp][3]);
                }
#pragma unroll
            for (int mt = 0; mt < 2; mt++)
#pragma unroll
                for (int ntp = 0; ntp < 4; ntp++) {
                    mma16816(acc[mt][2 * ntp],     al[mt], bhf[ntp][0], bhf[ntp][1]);
                    mma16816(acc[mt][2 * ntp + 1], al[mt], bhf[ntp][2], bhf[ntp][3]);
                }
        }
        __syncthreads();
    }

    const int g  = lane >> 2;
    const int t2 = lane & 3;
    if (EPI == 0) {
#pragma unroll
        for (int mt = 0; mt < 2; mt++) {
            int row = m0 + wm * 32 + mt * 16 + g;
#pragma unroll
            for (int nt = 0; nt < 8; nt++) {
                int col = n0 + wn * 64 + nt * 8 + t2 * 2;
                *reinterpret_cast<float2*>(&C[(size_t)row * N + col]) =
                    make_float2(acc[mt][nt][0], acc[mt][nt][1]);
                *reinterpret_cast<float2*>(&C[(size_t)(row + 8) * N + col]) =
                    make_float2(acc[mt][nt][2], acc[mt][nt][3]);
            }
        }
    } else if (EPI == 2) {
        // xi PERM store: dst ((step*3+gate)*GH+j)*4+b
#pragma unroll
        for (int mt = 0; mt < 2; mt++) {
#pragma unroll
            for (int rr = 0; rr < 2; rr++) {
                int row  = m0 + wm * 32 + mt * 16 + g + rr * 8;
                int b    = row >> 9;
                int st   = row & 511;
#pragma unroll
                for (int nt = 0; nt < 8; nt++) {
                    int col  = n0 + wn * 64 + nt * 8 + t2 * 2;
                    int gate = col >> 11;
                    int j    = col & 2047;
                    size_t base = ((size_t)(st * 3 + gate) * GH_ + j) * 4 + b;
                    C[base]     = acc[mt][nt][rr * 2 + 0];
                    C[base + 4] = acc[mt][nt][rr * 2 + 1];
                }
            }
        }
    } else {
        float s = 0.f;
#pragma unroll
        for (int mt = 0; mt < 2; mt++) {
            int row = m0 + wm * 32 + mt * 16 + g;
#pragma unroll
            for (int nt = 0; nt < 8; nt++) {
                int col = n0 + wn * 64 + nt * 8 + t2 * 2;
                float d0 = acc[mt][nt][0] - (row == col ? 1.f : 0.f);
                float d1 = acc[mt][nt][1] - (row == col + 1 ? 1.f : 0.f);
                float d2 = acc[mt][nt][2] - (row + 8 == col ? 1.f : 0.f);
                float d3 = acc[mt][nt][3] - (row + 8 == col + 1 ? 1.f : 0.f);
                s += d0 * d0 + d1 * d1 + d2 * d2 + d3 * d3;
            }
        }
        // symmetry: off-diagonal tiles stand in for their bitwise-equal mirror
        if (tile_x != tile_y) s *= 2.f;
        float* red = reinterpret_cast<float*>(smem);
        red[t] = s; __syncthreads();
        for (int o = 128; o > 0; o >>= 1) { if (t < o) red[t] += red[t + o]; __syncthreads(); }
        if (t == 0) g_losspart[blockIdx.x] = red[0];
    }
}

// ===== persistent GRU: grid 152, 1024 thr, split-K=2, SoA h (R8 EXACT) =====
__global__ void __launch_bounds__(1024) gru_kernel(const float* __restrict__ w_hh,
                                                   float* __restrict__ out_hn) {
    __shared__ float h_s[4][GH_];     // SoA: [batch][k] -> conflict-free float4 LDS
    __shared__ float part[16][12];
    const int t    = threadIdx.x;
    const int lane = t & 31;
    const int warp = t >> 5;          // 0..31
    const int pair = warp >> 1;       // 0..15
    const int half = warp & 1;
    const int nb   = gridDim.x;
    const int j    = pair * 152 + blockIdx.x;
    const bool valid = (j < GH_);
    unsigned target = 0;

    const float* wr = w_hh + (size_t)j * GH_;
    const float* wz = w_hh + (size_t)(GH_ + j) * GH_;
    const float* wn = w_hh + (size_t)(2 * GH_ + j) * GH_;
    const int kbase = half * 1024 + lane * 4;

    for (int step = 0; step < S_; step++) {
        if (step > 0) { target += nb; gsync(target); }
        const float* hsrc = g_hbuf + (step & 1) * (B_ * GH_);
        // SoA staging: thread t handles float4 index t (512 per batch)
        if (t < 512) {
#pragma unroll
            for (int b = 0; b < 4; b++) {
                float4 v = __ldcg(reinterpret_cast<const float4*>(hsrc + b * GH_) + t);
                *reinterpret_cast<float4*>(&h_s[b][t * 4]) = v;
            }
        }
        __syncthreads();
        float* hdst = g_hbuf + ((step + 1) & 1) * (B_ * GH_);

        float4 ar = make_float4(0.f, 0.f, 0.f, 0.f);
        float4 az = ar, an = ar;
        float xiv = 0.f;
        if (valid) {
            if (half == 0 && lane < 12)
                xiv = __ldcg(g_xi + ((size_t)(step * 3 + (lane >> 2)) * GH_ + j) * 4 + (lane & 3));

#pragma unroll
            for (int it = 0; it < 8; it++) {
                const int k = kbase + it * 128;
                float4 r4 = __ldcg(reinterpret_cast<const float4*>(wr + k));
                float4 z4 = __ldcg(reinterpret_cast<const float4*>(wz + k));
                float4 n4 = __ldcg(reinterpret_cast<const float4*>(wn + k));
                float4 hb0 = *reinterpret_cast<const float4*>(&h_s[0][k]);
                float4 hb1 = *reinterpret_cast<const float4*>(&h_s[1][k]);
                float4 hb2 = *reinterpret_cast<const float4*>(&h_s[2][k]);
                float4 hb3 = *reinterpret_cast<const float4*>(&h_s[3][k]);
                ar.x += r4.x*hb0.x + r4.y*hb0.y + r4.z*hb0.z + r4.w*hb0.w;
                ar.y += r4.x*hb1.x + r4.y*hb1.y + r4.z*hb1.z + r4.w*hb1.w;
                ar.z += r4.x*hb2.x + r4.y*hb2.y + r4.z*hb2.z + r4.w*hb2.w;
                ar.w += r4.x*hb3.x + r4.y*hb3.y + r4.z*hb3.z + r4.w*hb3.w;
                az.x += z4.x*hb0.x + z4.y*hb0.y + z4.z*hb0.z + z4.w*hb0.w;
                az.y += z4.x*hb1.x + z4.y*hb1.y + z4.z*hb1.z + z4.w*hb1.w;
                az.z += z4.x*hb2.x + z4.y*hb2.y + z4.z*hb2.z + z4.w*hb2.w;
                az.w += z4.x*hb3.x + z4.y*hb3.y + z4.z*hb3.z + z4.w*hb3.w;
                an.x += n4.x*hb0.x + n4.y*hb0.y + n4.z*hb0.z + n4.w*hb0.w;
                an.y += n4.x*hb1.x + n4.y*hb1.y + n4.z*hb1.z + n4.w*hb1.w;
                an.z += n4.x*hb2.x + n4.y*hb2.y + n4.z*hb2.z + n4.w*hb2.w;
                an.w += n4.x*hb3.x + n4.y*hb3.y + n4.z*hb3.z + n4.w*hb3.w;
            }

            ar.x = wsum(ar.x); ar.y = wsum(ar.y); ar.z = wsum(ar.z); ar.w = wsum(ar.w);
            az.x = wsum(az.x); az.y = wsum(az.y); az.z = wsum(az.z); az.w = wsum(az.w);
            an.x = wsum(an.x); an.y = wsum(an.y); an.z = wsum(an.z); an.w = wsum(an.w);
            if (half == 1 && lane == 0) {
                part[pair][0]  = ar.x; part[pair][1]  = ar.y;
                part[pair][2]  = ar.z; part[pair][3]  = ar.w;
                part[pair][4]  = az.x; part[pair][5]  = az.y;
                part[pair][6]  = az.z; part[pair][7]  = az.w;
                part[pair][8]  = an.x; part[pair][9]  = an.y;
                part[pair][10] = an.z; part[pair][11] = an.w;
            }
        }
        __syncthreads();
        if (valid && half == 0) {
            int b = lane & 3;
            float xr = __shfl_sync(0xffffffffu, xiv, b);
            float xz = __shfl_sync(0xffffffffu, xiv, 4 + b);
            float xn = __shfl_sync(0xffffffffu, xiv, 8 + b);
            if (lane < 4) {
                float arb = ((b & 1) ? ((b & 2) ? ar.w : ar.y) : ((b & 2) ? ar.z : ar.x))
                            + part[pair][b];
                float azb = ((b & 1) ? ((b & 2) ? az.w : az.y) : ((b & 2) ? az.z : az.x))
                            + part[pair][4 + b];
                float anb = ((b & 1) ? ((b & 2) ? an.w : an.y) : ((b & 2) ? an.z : an.x))
                            + part[pair][8 + b];
                float hob = h_s[b][j];
                float r = 1.f / (1.f + expf(-(xr + arb)));
                float z = 1.f / (1.f + expf(-(xz + azb)));
                float n = tanhf(xn + r * anb);
                float hv = (1.f - z) * n + z * hob;
                __stcg(hdst + b * GH_ + j, hv);
                __stcg(g_hs + (size_t)(b * S_ + step) * GH_ + j, hv);
            }
        }
    }
    target += nb; gsync(target);
    if (blockIdx.x == 0) {
        const float* hf = g_hbuf;   // 512 steps even -> buffer 0
        for (int i = t; i < B_ * GH_; i += 1024) out_hn[i] = __ldcg(hf + i);
    }
}

// -------- per-token: normalize rout, gram penalty, cosine sims --------
__global__ void __launch_bounds__(128) token_kernel(const float* __restrict__ expr,
                                                    float* __restrict__ cosO) {
    const int token = blockIdx.x;
    const int t = threadIdx.x, lane = t & 31, warp = t >> 5;
    __shared__ float sv[16 * 132];
    __shared__ float gm[16][17];
    __shared__ float pen_s[16];
    const float* rout = g_hs + (size_t)token * GH_;

    for (int e = warp; e < 16; e += 4) {
        float s = 0.f;
        for (int d = lane; d < 128; d += 32) { float v = rout[e * 128 + d]; s += v * v; }
        s = wsum(s);
        float inv = 1.f / fmaxf(sqrtf(s), 1e-12f);
        for (int d = lane; d < 128; d += 32) sv[e * 132 + d] = rout[e * 128 + d] * inv;
    }
    __syncthreads();
    for (int p = t; p < 256; p += 128) {
        int e = p >> 4, f = p & 15;
        float s = 0.f;
#pragma unroll 8
        for (int k = 0; k < 128; k++) s += sv[e * 132 + k] * sv[f * 132 + k];
        gm[e][f] = s;
    }
    __syncthreads();
    if (t < 16) {
        float s2 = 0.f;
        for (int f = 0; f < 16; f++) {
            float d = gm[t][f] - (t == f ? 1.f : 0.f);
            s2 += d * d;
        }
        float nrm = fmaxf(sqrtf(s2), 1e-12f);
        pen_s[t] = s2 / (nrm * nrm);
    }
    __syncthreads();
    if (t == 0) {
        float s = 0.f;
        for (int e = 0; e < 16; e++) s += pen_s[e];
        g_pen[token] = s;
    }
    for (int e = warp; e < 16; e += 4) {
        float dot = 0.f, ss = 0.f, rs = 0.f;
        for (int d = lane; d < 128; d += 32) {
            float ev = expr[(size_t)token * GH_ + e * 128 + d];
            float rv = sv[e * 132 + d];
            dot += ev * rv; ss += ev * ev; rs += rv * rv;
        }
        dot = wsum(dot); ss = wsum(ss); rs = wsum(rs);
        if (lane == 0) {
            float en = fmaxf(sqrtf(ss), 1e-8f);
            float rn = fmaxf(sqrtf(rs), 1e-8f);
            cosO[token * 16 + e] = 1.f - dot / (en * rn);
        }
    }
}

// -------- penalty mean + load-balance adjustment --------
__global__ void finalize_kernel(const float* __restrict__ ema, float* __restrict__ out) {
    __shared__ float red[256];
    int t = threadIdx.x;
    float s = 0.f;
    for (int i = t; i < NTOK; i += 256) s += g_pen[i];
    red[t] = s; __syncthreads();
    for (int o = 128; o > 0; o >>= 1) { if (t < o) red[t] += red[t + o]; __syncthreads(); }
    if (t == 0) {
        float pen = red[0] / (float)NTOK;
        g_scal[0] = pen;
        out[O_PEN] = pen;
        float tot = 0.f;
        for (int e = 0; e < 16; e++) tot += ema[e];
        for (int e = 0; e < 16; e++) {
            float sc = (tot > 0.f) ? ema[e] / fmaxf(tot, 1e-12f) : 0.f;
            g_scal[1 + e] = sc * 0.01f * 16.f;
        }
    }
}

// -------- top-2 + softmax + adjustment --------
__global__ void topk_kernel(const float* __restrict__ cosv, float* __restrict__ out) {
    int token = blockIdx.x * blockDim.x + threadIdx.x;
    if (token >= NTOK) return;
    float mul = 1.f + g_scal[0];
    float dv[16];
#pragma unroll
    for (int e = 0; e < 16; e++) dv[e] = cosv[token * 16 + e] * mul;
    int i0 = 0; float v0 = dv[0];
#pragma unroll
    for (int e = 1; e < 16; e++) if (dv[e] > v0) { v0 = dv[e]; i0 = e; }
    int i1 = (i0 == 0) ? 1 : 0; float v1 = dv[i1];
#pragma unroll
    for (int e = 0; e < 16; e++) if (e != i0 && dv[e] > v1) { v1 = dv[e]; i1 = e; }
    float e1  = expf(v1 - v0);
    float inv = 1.f / (1.f + e1);
    out[O_MULT + token * 2 + 0] = inv - g_scal[1 + i0];
    out[O_MULT + token * 2 + 1] = e1 * inv - g_scal[1 + i1];
    out[O_SEL + token * 2 + 0] = (float)i0;
    out[O_SEL + token * 2 + 1] = (float)i1;
}

__global__ void wloss_reduce_kernel(float* __restrict__ out) {
    __shared__ float red[256];
    int t = threadIdx.x;
    float s = (t < 136) ? g_losspart[t] : 0.f;
    red[t] = s; __syncthreads();
    for (int o = 128; o > 0; o >>= 1) { if (t < o) red[t] += red[t + o]; __syncthreads(); }
    if (t == 0) out[O_LOSS] = red[0] / ((float)GH_ * (float)GH_);
}

// -------- host --------
extern "C" void kernel_launch(void* const* d_in, const int* in_sizes, int n_in,
                              void* d_out, int out_size) {
    const float* x      = (const float*)d_in[0];
    const float* hn     = (const float*)d_in[1];
    const float* w_ih   = (const float*)d_in[2];
    const float* w_hh   = (const float*)d_in[3];
    const float* w_expr = (const float*)d_in[4];
    const float* ema    = (const float*)d_in[5];
    float* out = (float*)d_out;

    void* p = 0;
    cudaGetSymbolAddress(&p, g_xi);  float* xi = (float*)p;
    __nv_bfloat16 *xh, *xl, *wih_h, *wih_l, *weT_h, *weT_l;
    cudaGetSymbolAddress(&p, g_xh);    xh = (__nv_bfloat16*)p;
    cudaGetSymbolAddress(&p, g_xl);    xl = (__nv_bfloat16*)p;
    cudaGetSymbolAddress(&p, g_wih_h); wih_h = (__nv_bfloat16*)p;
    cudaGetSymbolAddress(&p, g_wih_l); wih_l = (__nv_bfloat16*)p;
    cudaGetSymbolAddress(&p, g_weT_h); weT_h = (__nv_bfloat16*)p;
    cudaGetSymbolAddress(&p, g_weT_l); weT_l = (__nv_bfloat16*)p;

    static int smem_set = 0;
    if (!smem_set) {
        cudaFuncSetAttribute(mma_gemm_kernel<0>, cudaFuncAttributeMaxDynamicSharedMemorySize, SMTOT);
        cudaFuncSetAttribute(mma_gemm_kernel<1>, cudaFuncAttributeMaxDynamicSharedMemorySize, SMTOT);
        cudaFuncSetAttribute(mma_gemm_kernel<2>, cudaFuncAttributeMaxDynamicSharedMemorySize, SMTOT);
        smem_set = 1;
    }

    init_kernel<<<32, 256>>>(hn);

    split_kernel<<<(NTOK * H_ / 4 + 255) / 256, 256>>>(x, xh, xl, NTOK * H_ / 4);
    split_kernel<<<(G3_ * H_ / 4 + 255) / 256, 256>>>(w_ih, wih_h, wih_l, G3_ * H_ / 4);
    tsplit_kernel<<<dim3(GH_ / 32, H_ / 32), dim3(32, 8)>>>(w_expr, weT_h, weT_l);

    // xi = x @ w_ih^T, stored in PERM layout for the GRU
    mma_gemm_kernel<2><<<dim3(G3_ / 128, NTOK / 128), 256, SMTOT>>>(
        xh, xl, wih_h, wih_l, xi, G3_, H_);
    // expr = x @ w_expr
    mma_gemm_kernel<0><<<dim3(GH_ / 128, NTOK / 128), 256, SMTOT>>>(
        xh, xl, weT_h, weT_l, out + O_EXPR, GH_, H_);

    gru_kernel<<<152, 1024>>>(w_hh, out + O_HN);

    token_kernel<<<NTOK, 128>>>(out + O_EXPR, out + O_COS);
    finalize_kernel<<<1, 256>>>(ema, out);
    topk_kernel<<<8, 256>>>(out + O_COS, out);

    // wloss: W^T W, upper-triangle tiles only (symmetry, mirror tiles bitwise equal)
    mma_gemm_kernel<1><<<136, 256, SMTOT>>>(
        weT_h, weT_l, weT_h, weT_l, nullptr, GH_, H_);
    wloss_reduce_kernel<<<1, 256>>>(out);
}

// round 17
// speedup vs baseline: 1.0562x; 1.0063x over previous
#include <cuda_runtime.h>
#include <cuda_bf16.h>
#include <math.h>
#include <stdint.h>

// Problem dims
#define B_   4
#define S_   512
#define H_   2048
#define E_   16
#define D_   128
#define GH_  2048
#define G3_  6144
#define NTOK 2048   // B_*S_

// Output layout (flat f32 concat, reference return order)
#define O_MULT 0
#define O_SEL  4096
#define O_EXPR 8192
#define O_HN   4202496
#define O_PEN  4210688
#define O_COS  4210689
#define O_LOSS 4243457

// -------- device scratch --------
__device__ float    g_xi[NTOK * G3_];      // PERM layout: [step][gate][j][b]
__device__ float    g_hs[NTOK * GH_];
__device__ float    g_hbuf[2 * B_ * GH_];
__device__ float    g_pen[NTOK];
__device__ float    g_scal[32];
__device__ float    g_losspart[1024];
__device__ unsigned g_ctr;

// bf16 hi/lo split operands
__device__ __align__(16) __nv_bfloat16 g_xh[NTOK * H_];
__device__ __align__(16) __nv_bfloat16 g_xl[NTOK * H_];
__device__ __align__(16) __nv_bfloat16 g_wih_h[G3_ * H_];
__device__ __align__(16) __nv_bfloat16 g_wih_l[G3_ * H_];
__device__ __align__(16) __nv_bfloat16 g_weT_h[GH_ * H_];
__device__ __align__(16) __nv_bfloat16 g_weT_l[GH_ * H_];

// -------- helpers --------
__device__ __forceinline__ float wsum(float v) {
#pragma unroll
    for (int o = 16; o > 0; o >>= 1) v += __shfl_xor_sync(0xffffffffu, v, o);
    return v;
}
__device__ __forceinline__ uint32_t smem_u32(const void* p) {
    uint32_t a;
    asm("{ .reg .u64 t; cvta.to.shared.u64 t, %1; cvt.u32.u64 %0, t; }"
        : "=r"(a) : "l"(p));
    return a;
}
__device__ __forceinline__ void ldsm4(uint32_t addr, uint32_t* r) {
    asm volatile("ldmatrix.sync.aligned.m8n8.x4.shared.b16 {%0,%1,%2,%3}, [%4];"
                 : "=r"(r[0]), "=r"(r[1]), "=r"(r[2]), "=r"(r[3]) : "r"(addr));
}
__device__ __forceinline__ void mma16816(float* c, const uint32_t* a,
                                         uint32_t b0, uint32_t b1) {
    asm volatile(
        "mma.sync.aligned.m16n8k16.row.col.f32.bf16.bf16.f32 "
        "{%0,%1,%2,%3}, {%4,%5,%6,%7}, {%8,%9}, {%0,%1,%2,%3};"
        : "+f"(c[0]), "+f"(c[1]), "+f"(c[2]), "+f"(c[3])
        : "r"(a[0]), "r"(a[1]), "r"(a[2]), "r"(a[3]), "r"(b0), "r"(b1));
}
__device__ __forceinline__ void cpa16(uint32_t s, const void* g) {
    asm volatile("cp.async.cg.shared.global [%0], [%1], 16;" :: "r"(s), "l"(g));
}
__device__ __forceinline__ void cpa_commit() {
    asm volatile("cp.async.commit_group;");
}
template <int N>
__device__ __forceinline__ void cpa_wait() {
    asm volatile("cp.async.wait_group %0;" :: "n"(N));
}
// R8-proven atomic-counter grid barrier (exact).
__device__ __forceinline__ void gsync(unsigned target) {
    __threadfence();
    __syncthreads();
    if (threadIdx.x == 0) {
        atomicAdd(&g_ctr, 1u);
        volatile unsigned* p = &g_ctr;
        while (*p < target) { __nanosleep(32); }
    }
    __syncthreads();
}

// -------- init --------
__global__ void init_kernel(const float* __restrict__ hn) {
    int i = blockIdx.x * 256 + threadIdx.x;
    if (i == 0) g_ctr = 0u;
    if (i < B_ * GH_) g_hbuf[i] = hn[i];
}

// -------- split f32 -> bf16 hi/lo (4 float4 per thread for MLP) --------
__global__ void split_kernel(const float* __restrict__ src,
                             __nv_bfloat16* __restrict__ hi,
                             __nv_bfloat16* __restrict__ lo, int n4) {
    const int base   = blockIdx.x * 1024 + threadIdx.x;
    const int stride = gridDim.x * 1024;
    (void)stride;
    float4 v[4];
    int idx[4];
#pragma unroll
    for (int f = 0; f < 4; f++) {
        idx[f] = base + f * 256;
        if (idx[f] < n4) v[f] = reinterpret_cast<const float4*>(src)[idx[f]];
    }
#pragma unroll
    for (int f = 0; f < 4; f++) {
        if (idx[f] >= n4) continue;
        __nv_bfloat16 h0 = __float2bfloat16(v[f].x), h1 = __float2bfloat16(v[f].y);
        __nv_bfloat16 h2 = __float2bfloat16(v[f].z), h3 = __float2bfloat16(v[f].w);
        __nv_bfloat16 l0 = __float2bfloat16(v[f].x - __bfloat162float(h0));
        __nv_bfloat16 l1 = __float2bfloat16(v[f].y - __bfloat162float(h1));
        __nv_bfloat16 l2 = __float2bfloat16(v[f].z - __bfloat162float(h2));
        __nv_bfloat16 l3 = __float2bfloat16(v[f].w - __bfloat162float(h3));
        reinterpret_cast<__nv_bfloat162*>(hi)[2 * idx[f]]     = __nv_bfloat162(h0, h1);
        reinterpret_cast<__nv_bfloat162*>(hi)[2 * idx[f] + 1] = __nv_bfloat162(h2, h3);
        reinterpret_cast<__nv_bfloat162*>(lo)[2 * idx[f]]     = __nv_bfloat162(l0, l1);
        reinterpret_cast<__nv_bfloat162*>(lo)[2 * idx[f] + 1] = __nv_bfloat162(l2, l3);
    }
}

// -------- transpose + split: W[H,GH] -> T[GH,H] bf16 hi/lo --------
__global__ void tsplit_kernel(const float* __restrict__ W,
                              __nv_bfloat16* __restrict__ Th,
                              __nv_bfloat16* __restrict__ Tl) {
    __shared__ float t[32][33];
    int gc = blockIdx.x * 32;
    int gr = blockIdx.y * 32;
    int tx = threadIdx.x, ty = threadIdx.y;
#pragma unroll
    for (int r = 0; r < 32; r += 8)
        t[ty + r][tx] = W[(size_t)(gr + ty + r) * GH_ + gc + tx];
    __syncthreads();
#pragma unroll
    for (int r = 0; r < 32; r += 8) {
        float v = t[tx][ty + r];
        __nv_bfloat16 h = __float2bfloat16(v);
        __nv_bfloat16 l = __float2bfloat16(v - __bfloat162float(h));
        size_t o = (size_t)(gc + ty + r) * H_ + gr + tx;
        Th[o] = h; Tl[o] = l;
    }
}

// ========== mma.sync GEMM: C[M,N] = A @ B^T, bf16 hi/lo 3-term split =====
// EPI==0: store C.  EPI==1: wloss upper-triangle tile, weighted sum((C-I)^2).
// EPI==2: store xi PERM layout.
#define ROWB  80
#define TILEB (128 * ROWB)       // 10240
#define BUFB  (4 * TILEB)        // 40960
#define SMTOT (2 * BUFB)         // 81920

template <int EPI>
__global__ void __launch_bounds__(256) mma_gemm_kernel(
    const __nv_bfloat16* __restrict__ Ah, const __nv_bfloat16* __restrict__ Al,
    const __nv_bfloat16* __restrict__ Bh, const __nv_bfloat16* __restrict__ Bl,
    float* __restrict__ C, int N, int K)
{
    extern __shared__ char smem[];
    const uint32_t sb = smem_u32(smem);
    const int t    = threadIdx.x;
    const int lane = t & 31;
    const int w    = t >> 5;
    const int wm   = w >> 1;
    const int wn   = w & 1;

    int tile_x = blockIdx.x, tile_y = blockIdx.y;
    if (EPI == 1) {
        // upper-triangle tile map: bid -> (ty, tx), tx >= ty, 16x16 tiles
        int rem = blockIdx.x, r = 0;
        while (rem >= 16 - r) { rem -= 16 - r; r++; }
        tile_y = r; tile_x = r + rem;
    }
    const int n0 = tile_x * 128;
    const int m0 = tile_y * 128;

    const __nv_bfloat16* srcs[4] = {
        Ah + (size_t)m0 * K, Al + (size_t)m0 * K,
        Bh + (size_t)n0 * K, Bl + (size_t)n0 * K };

    const int srow0 = t >> 2;
    const int srow1 = srow0 + 64;
    const int sc16  = t & 3;

    float acc[2][8][4];
#pragma unroll
    for (int i = 0; i < 2; i++)
#pragma unroll
        for (int j = 0; j < 8; j++)
#pragma unroll
            for (int c = 0; c < 4; c++) acc[i][j][c] = 0.f;

    const uint32_t a_row = wm * 32 + (lane & 15);
    const uint32_t a_cs  = lane >> 4;
    const uint32_t b_row = wn * 64 + ((lane >> 4) << 3) + (lane & 7);
    const uint32_t b_cs  = (lane >> 3) & 1;

    const int NCH = K >> 5;

    auto stage = [&](int ch, int buf) {
        const uint32_t bb = sb + buf * BUFB;
        const int koff = ch * 32 + sc16 * 8;
#pragma unroll
        for (int o = 0; o < 4; o++) {
            cpa16(bb + o * TILEB + srow0 * ROWB + sc16 * 16,
                  srcs[o] + (size_t)srow0 * K + koff);
            cpa16(bb + o * TILEB + srow1 * ROWB + sc16 * 16,
                  srcs[o] + (size_t)srow1 * K + koff);
        }
        cpa_commit();
    };

    stage(0, 0);
#pragma unroll 1
    for (int ch = 0; ch < NCH; ch++) {
        const int buf = ch & 1;
        if (ch + 1 < NCH) { stage(ch + 1, buf ^ 1); cpa_wait<1>(); }
        else              { cpa_wait<0>(); }
        __syncthreads();

        const uint32_t bb = sb + buf * BUFB;
#pragma unroll
        for (int kt = 0; kt < 2; kt++) {
            uint32_t ah[2][4], al[2][4], bhf[4][4], blf[4][4];
#pragma unroll
            for (int mt = 0; mt < 2; mt++) {
                uint32_t off = bb + (a_row + mt * 16) * ROWB + (kt * 2 + a_cs) * 16;
                ldsm4(off, ah[mt]);
                ldsm4(off + TILEB, al[mt]);
            }
#pragma unroll
            for (int ntp = 0; ntp < 4; ntp++) {
                uint32_t off = bb + 2 * TILEB + (b_row + ntp * 16) * ROWB + (kt * 2 + b_cs) * 16;
                ldsm4(off, bhf[ntp]);
                ldsm4(off + TILEB, blf[ntp]);
            }
#pragma unroll
            for (int mt = 0; mt < 2; mt++)
#pragma unroll
                for (int ntp = 0; ntp < 4; ntp++) {
                    mma16816(acc[mt][2 * ntp],     ah[mt], bhf[ntp][0], bhf[ntp][1]);
                    mma16816(acc[mt][2 * ntp + 1], ah[mt], bhf[ntp][2], bhf[ntp][3]);
                }
#pragma unroll
            for (int mt = 0; mt < 2; mt++)
#pragma unroll
                for (int ntp = 0; ntp < 4; ntp++) {
                    mma16816(acc[mt][2 * ntp],     ah[mt], blf[ntp][0], blf[ntp][1]);
                    mma16816(acc[mt][2 * ntp + 1], ah[mt], blf[ntp][2], blf[ntp][3]);
                }
#pragma unroll
            for (int mt = 0; mt < 2; mt++)
#pragma unroll
                for (int ntp = 0; ntp < 4; ntp++) {
                    mma16816(acc[mt][2 * ntp],     al[mt], bhf[ntp][0], bhf[ntp][1]);
                    mma16816(acc[mt][2 * ntp + 1], al[mt], bhf[ntp][2], bhf[ntp][3]);
                }
        }
        __syncthreads();
    }

    const int g  = lane >> 2;
    const int t2 = lane & 3;
    if (EPI == 0) {
#pragma unroll
        for (int mt = 0; mt < 2; mt++) {
            int row = m0 + wm * 32 + mt * 16 + g;
#pragma unroll
            for (int nt = 0; nt < 8; nt++) {
                int col = n0 + wn * 64 + nt * 8 + t2 * 2;
                *reinterpret_cast<float2*>(&C[(size_t)row * N + col]) =
                    make_float2(acc[mt][nt][0], acc[mt][nt][1]);
                *reinterpret_cast<float2*>(&C[(size_t)(row + 8) * N + col]) =
                    make_float2(acc[mt][nt][2], acc[mt][nt][3]);
            }
        }
    } else if (EPI == 2) {
        // xi PERM store: dst ((step*3+gate)*GH+j)*4+b
#pragma unroll
        for (int mt = 0; mt < 2; mt++) {
#pragma unroll
            for (int rr = 0; rr < 2; rr++) {
                int row  = m0 + wm * 32 + mt * 16 + g + rr * 8;
                int b    = row >> 9;
                int st   = row & 511;
#pragma unroll
                for (int nt = 0; nt < 8; nt++) {
                    int col  = n0 + wn * 64 + nt * 8 + t2 * 2;
                    int gate = col >> 11;
                    int j    = col & 2047;
                    size_t base = ((size_t)(st * 3 + gate) * GH_ + j) * 4 + b;
                    C[base]     = acc[mt][nt][rr * 2 + 0];
                    C[base + 4] = acc[mt][nt][rr * 2 + 1];
                }
            }
        }
    } else {
        float s = 0.f;
#pragma unroll
        for (int mt = 0; mt < 2; mt++) {
            int row = m0 + wm * 32 + mt * 16 + g;
#pragma unroll
            for (int nt = 0; nt < 8; nt++) {
                int col = n0 + wn * 64 + nt * 8 + t2 * 2;
                float d0 = acc[mt][nt][0] - (row == col ? 1.f : 0.f);
                float d1 = acc[mt][nt][1] - (row == col + 1 ? 1.f : 0.f);
                float d2 = acc[mt][nt][2] - (row + 8 == col ? 1.f : 0.f);
                float d3 = acc[mt][nt][3] - (row + 8 == col + 1 ? 1.f : 0.f);
                s += d0 * d0 + d1 * d1 + d2 * d2 + d3 * d3;
            }
        }
        // symmetry: off-diagonal tiles stand in for their bitwise-equal mirror
        if (tile_x != tile_y) s *= 2.f;
        float* red = reinterpret_cast<float*>(smem);
        red[t] = s; __syncthreads();
        for (int o = 128; o > 0; o >>= 1) { if (t < o) red[t] += red[t + o]; __syncthreads(); }
        if (t == 0) g_losspart[blockIdx.x] = red[0];
    }
}

// ===== persistent GRU: grid 152, 1024 thr, split-K=2, SoA h (R8 EXACT) =====
__global__ void __launch_bounds__(1024) gru_kernel(const float* __restrict__ w_hh,
                                                   float* __restrict__ out_hn) {
    __shared__ float h_s[4][GH_];     // SoA: [batch][k] -> conflict-free float4 LDS
    __shared__ float part[16][12];
    const int t    = threadIdx.x;
    const int lane = t & 31;
    const int warp = t >> 5;          // 0..31
    const int pair = warp >> 1;       // 0..15
    const int half = warp & 1;
    const int nb   = gridDim.x;
    const int j    = pair * 152 + blockIdx.x;
    const bool valid = (j < GH_);
    unsigned target = 0;

    const float* wr = w_hh + (size_t)j * GH_;
    const float* wz = w_hh + (size_t)(GH_ + j) * GH_;
    const float* wn = w_hh + (size_t)(2 * GH_ + j) * GH_;
    const int kbase = half * 1024 + lane * 4;

    for (int step = 0; step < S_; step++) {
        if (step > 0) { target += nb; gsync(target); }
        const float* hsrc = g_hbuf + (step & 1) * (B_ * GH_);
        // SoA staging: thread t handles float4 index t (512 per batch)
        if (t < 512) {
#pragma unroll
            for (int b = 0; b < 4; b++) {
                float4 v = __ldcg(reinterpret_cast<const float4*>(hsrc + b * GH_) + t);
                *reinterpret_cast<float4*>(&h_s[b][t * 4]) = v;
            }
        }
        __syncthreads();
        float* hdst = g_hbuf + ((step + 1) & 1) * (B_ * GH_);

        float4 ar = make_float4(0.f, 0.f, 0.f, 0.f);
        float4 az = ar, an = ar;
        float xiv = 0.f;
        if (valid) {
            if (half == 0 && lane < 12)
                xiv = __ldcg(g_xi + ((size_t)(step * 3 + (lane >> 2)) * GH_ + j) * 4 + (lane & 3));

#pragma unroll
            for (int it = 0; it < 8; it++) {
                const int k = kbase + it * 128;
                float4 r4 = __ldcg(reinterpret_cast<const float4*>(wr + k));
                float4 z4 = __ldcg(reinterpret_cast<const float4*>(wz + k));
                float4 n4 = __ldcg(reinterpret_cast<const float4*>(wn + k));
                float4 hb0 = *reinterpret_cast<const float4*>(&h_s[0][k]);
                float4 hb1 = *reinterpret_cast<const float4*>(&h_s[1][k]);
                float4 hb2 = *reinterpret_cast<const float4*>(&h_s[2][k]);
                float4 hb3 = *reinterpret_cast<const float4*>(&h_s[3][k]);
                ar.x += r4.x*hb0.x + r4.y*hb0.y + r4.z*hb0.z + r4.w*hb0.w;
                ar.y += r4.x*hb1.x + r4.y*hb1.y + r4.z*hb1.z + r4.w*hb1.w;
                ar.z += r4.x*hb2.x + r4.y*hb2.y + r4.z*hb2.z + r4.w*hb2.w;
                ar.w += r4.x*hb3.x + r4.y*hb3.y + r4.z*hb3.z + r4.w*hb3.w;
                az.x += z4.x*hb0.x + z4.y*hb0.y + z4.z*hb0.z + z4.w*hb0.w;
                az.y += z4.x*hb1.x + z4.y*hb1.y + z4.z*hb1.z + z4.w*hb1.w;
                az.z += z4.x*hb2.x + z4.y*hb2.y + z4.z*hb2.z + z4.w*hb2.w;
                az.w += z4.x*hb3.x + z4.y*hb3.y + z4.z*hb3.z + z4.w*hb3.w;
                an.x += n4.x*hb0.x + n4.y*hb0.y + n4.z*hb0.z + n4.w*hb0.w;
                an.y += n4.x*hb1.x + n4.y*hb1.y + n4.z*hb1.z + n4.w*hb1.w;
                an.z += n4.x*hb2.x + n4.y*hb2.y + n4.z*hb2.z + n4.w*hb2.w;
                an.w += n4.x*hb3.x + n4.y*hb3.y + n4.z*hb3.z + n4.w*hb3.w;
            }

            ar.x = wsum(ar.x); ar.y = wsum(ar.y); ar.z = wsum(ar.z); ar.w = wsum(ar.w);
            az.x = wsum(az.x); az.y = wsum(az.y); az.z = wsum(az.z); az.w = wsum(az.w);
            an.x = wsum(an.x); an.y = wsum(an.y); an.z = wsum(an.z); an.w = wsum(an.w);
            if (half == 1 && lane == 0) {
                part[pair][0]  = ar.x; part[pair][1]  = ar.y;
                part[pair][2]  = ar.z; part[pair][3]  = ar.w;
                part[pair][4]  = az.x; part[pair][5]  = az.y;
                part[pair][6]  = az.z; part[pair][7]  = az.w;
                part[pair][8]  = an.x; part[pair][9]  = an.y;
                part[pair][10] = an.z; part[pair][11] = an.w;
            }
        }
        __syncthreads();
        if (valid && half == 0) {
            int b = lane & 3;
            float xr = __shfl_sync(0xffffffffu, xiv, b);
            float xz = __shfl_sync(0xffffffffu, xiv, 4 + b);
            float xn = __shfl_sync(0xffffffffu, xiv, 8 + b);
            if (lane < 4) {
                float arb = ((b & 1) ? ((b & 2) ? ar.w : ar.y) : ((b & 2) ? ar.z : ar.x))
                            + part[pair][b];
                float azb = ((b & 1) ? ((b & 2) ? az.w : az.y) : ((b & 2) ? az.z : az.x))
                            + part[pair][4 + b];
                float anb = ((b & 1) ? ((b & 2) ? an.w : an.y) : ((b & 2) ? an.z : an.x))
                            + part[pair][8 + b];
                float hob = h_s[b][j];
                float r = 1.f / (1.f + expf(-(xr + arb)));
                float z = 1.f / (1.f + expf(-(xz + azb)));
                float n = tanhf(xn + r * anb);
                float hv = (1.f - z) * n + z * hob;
                __stcg(hdst + b * GH_ + j, hv);
                __stcg(g_hs + (size_t)(b * S_ + step) * GH_ + j, hv);
            }
        }
    }
    target += nb; gsync(target);
    if (blockIdx.x == 0) {
        const float* hf = g_hbuf;   // 512 steps even -> buffer 0
        for (int i = t; i < B_ * GH_; i += 1024) out_hn[i] = __ldcg(hf + i);
    }
}

// -------- per-token: normalize rout, gram penalty, cosine sims --------
__global__ void __launch_bounds__(128) token_kernel(const float* __restrict__ expr,
                                                    float* __restrict__ cosO) {
    const int token = blockIdx.x;
    const int t = threadIdx.x, lane = t & 31, warp = t >> 5;
    __shared__ float sv[16 * 132];
    __shared__ float gm[16][17];
    __shared__ float pen_s[16];
    const float* rout = g_hs + (size_t)token * GH_;

    for (int e = warp; e < 16; e += 4) {
        float s = 0.f;
        for (int d = lane; d < 128; d += 32) { float v = rout[e * 128 + d]; s += v * v; }
        s = wsum(s);
        float inv = 1.f / fmaxf(sqrtf(s), 1e-12f);
        for (int d = lane; d < 128; d += 32) sv[e * 132 + d] = rout[e * 128 + d] * inv;
    }
    __syncthreads();
    for (int p = t; p < 256; p += 128) {
        int e = p >> 4, f = p & 15;
        float s = 0.f;
#pragma unroll 8
        for (int k = 0; k < 128; k++) s += sv[e * 132 + k] * sv[f * 132 + k];
        gm[e][f] = s;
    }
    __syncthreads();
    if (t < 16) {
        float s2 = 0.f;
        for (int f = 0; f < 16; f++) {
            float d = gm[t][f] - (t == f ? 1.f : 0.f);
            s2 += d * d;
        }
        float nrm = fmaxf(sqrtf(s2), 1e-12f);
        pen_s[t] = s2 / (nrm * nrm);
    }
    __syncthreads();
    if (t == 0) {
        float s = 0.f;
        for (int e = 0; e < 16; e++) s += pen_s[e];
        g_pen[token] = s;
    }
    for (int e = warp; e < 16; e += 4) {
        float dot = 0.f, ss = 0.f, rs = 0.f;
        for (int d = lane; d < 128; d += 32) {
            float ev = expr[(size_t)token * GH_ + e * 128 + d];
            float rv = sv[e * 132 + d];
            dot += ev * rv; ss += ev * ev; rs += rv * rv;
        }
        dot = wsum(dot); ss = wsum(ss); rs = wsum(rs);
        if (lane == 0) {
            float en = fmaxf(sqrtf(ss), 1e-8f);
            float rn = fmaxf(sqrtf(rs), 1e-8f);
            cosO[token * 16 + e] = 1.f - dot / (en * rn);
        }
    }
}

// -------- penalty mean + load-balance adjustment --------
__global__ void finalize_kernel(const float* __restrict__ ema, float* __restrict__ out) {
    __shared__ float red[256];
    int t = threadIdx.x;
    float s = 0.f;
    for (int i = t; i < NTOK; i += 256) s += g_pen[i];
    red[t] = s; __syncthreads();
    for (int o = 128; o > 0; o >>= 1) { if (t < o) red[t] += red[t + o]; __syncthreads(); }
    if (t == 0) {
        float pen = red[0] / (float)NTOK;
        g_scal[0] = pen;
        out[O_PEN] = pen;
        float tot = 0.f;
        for (int e = 0; e < 16; e++) tot += ema[e];
        for (int e = 0; e < 16; e++) {
            float sc = (tot > 0.f) ? ema[e] / fmaxf(tot, 1e-12f) : 0.f;
            g_scal[1 + e] = sc * 0.01f * 16.f;
        }
    }
}

// -------- top-2 + softmax + adjustment --------
__global__ void topk_kernel(const float* __restrict__ cosv, float* __restrict__ out) {
    int token = blockIdx.x * blockDim.x + threadIdx.x;
    if (token >= NTOK) return;
    float mul = 1.f + g_scal[0];
    float dv[16];
#pragma unroll
    for (int e = 0; e < 16; e++) dv[e] = cosv[token * 16 + e] * mul;
    int i0 = 0; float v0 = dv[0];
#pragma unroll
    for (int e = 1; e < 16; e++) if (dv[e] > v0) { v0 = dv[e]; i0 = e; }
    int i1 = (i0 == 0) ? 1 : 0; float v1 = dv[i1];
#pragma unroll
    for (int e = 0; e < 16; e++) if (e != i0 && dv[e] > v1) { v1 = dv[e]; i1 = e; }
    float e1  = expf(v1 - v0);
    float inv = 1.f / (1.f + e1);
    out[O_MULT + token * 2 + 0] = inv - g_scal[1 + i0];
    out[O_MULT + token * 2 + 1] = e1 * inv - g_scal[1 + i1];
    out[O_SEL + token * 2 + 0] = (float)i0;
    out[O_SEL + token * 2 + 1] = (float)i1;
}

__global__ void wloss_reduce_kernel(float* __restrict__ out) {
    __shared__ float red[256];
    int t = threadIdx.x;
    float s = (t < 136) ? g_losspart[t] : 0.f;
    red[t] = s; __syncthreads();
    for (int o = 128; o > 0; o >>= 1) { if (t < o) red[t] += red[t + o]; __syncthreads(); }
    if (t == 0) out[O_LOSS] = red[0] / ((float)GH_ * (float)GH_);
}

// -------- host --------
extern "C" void kernel_launch(void* const* d_in, const int* in_sizes, int n_in,
                              void* d_out, int out_size) {
    const float* x      = (const float*)d_in[0];
    const float* hn     = (const float*)d_in[1];
    const float* w_ih   = (const float*)d_in[2];
    const float* w_hh   = (const float*)d_in[3];
    const float* w_expr = (const float*)d_in[4];
    const float* ema    = (const float*)d_in[5];
    float* out = (float*)d_out;

    void* p = 0;
    cudaGetSymbolAddress(&p, g_xi);  float* xi = (float*)p;
    __nv_bfloat16 *xh, *xl, *wih_h, *wih_l, *weT_h, *weT_l;
    cudaGetSymbolAddress(&p, g_xh);    xh = (__nv_bfloat16*)p;
    cudaGetSymbolAddress(&p, g_xl);    xl = (__nv_bfloat16*)p;
    cudaGetSymbolAddress(&p, g_wih_h); wih_h = (__nv_bfloat16*)p;
    cudaGetSymbolAddress(&p, g_wih_l); wih_l = (__nv_bfloat16*)p;
    cudaGetSymbolAddress(&p, g_weT_h); weT_h = (__nv_bfloat16*)p;
    cudaGetSymbolAddress(&p, g_weT_l); weT_l = (__nv_bfloat16*)p;

    static int smem_set = 0;
    if (!smem_set) {
        cudaFuncSetAttribute(mma_gemm_kernel<0>, cudaFuncAttributeMaxDynamicSharedMemorySize, SMTOT);
        cudaFuncSetAttribute(mma_gemm_kernel<1>, cudaFuncAttributeMaxDynamicSharedMemorySize, SMTOT);
        cudaFuncSetAttribute(mma_gemm_kernel<2>, cudaFuncAttributeMaxDynamicSharedMemorySize, SMTOT);
        smem_set = 1;
    }

    init_kernel<<<32, 256>>>(hn);

    // splits with 4 float4 per thread (MLP=4)
    split_kernel<<<(NTOK * H_ / 4 + 1023) / 1024, 256>>>(x, xh, xl, NTOK * H_ / 4);
    split_kernel<<<(G3_ * H_ / 4 + 1023) / 1024, 256>>>(w_ih, wih_h, wih_l, G3_ * H_ / 4);
    tsplit_kernel<<<dim3(GH_ / 32, H_ / 32), dim3(32, 8)>>>(w_expr, weT_h, weT_l);

    // xi = x @ w_ih^T, stored in PERM layout for the GRU
    mma_gemm_kernel<2><<<dim3(G3_ / 128, NTOK / 128), 256, SMTOT>>>(
        xh, xl, wih_h, wih_l, xi, G3_, H_);
    // expr = x @ w_expr
    mma_gemm_kernel<0><<<dim3(GH_ / 128, NTOK / 128), 256, SMTOT>>>(
        xh, xl, weT_h, weT_l, out + O_EXPR, GH_, H_);

    gru_kernel<<<152, 1024>>>(w_hh, out + O_HN);

    token_kernel<<<NTOK, 128>>>(out + O_EXPR, out + O_COS);
    finalize_kernel<<<1, 256>>>(ema, out);
    topk_kernel<<<8, 256>>>(out + O_COS, out);

    // wloss: W^T W, upper-triangle tiles only (symmetry, mirror tiles bitwise equal)
    mma_gemm_kernel<1><<<136, 256, SMTOT>>>(
        weT_h, weT_l, weT_h, weT_l, nullptr, GH_, H_);
    wloss_reduce_kernel<<<1, 256>>>(out);
}